// round 9
// baseline (speedup 1.0000x reference)
#include <cuda_runtime.h>
#include <cuda_fp16.h>
#include <math.h>
#include <stdint.h>

#define S_ 196
#define B_ 64
#define E_ 1024
#define D_ 1800
#define W_ 512
#define V_ 32000
#define WE_ (W_ + E_)       // 1536
#define DE_ (D_ + E_)       // 2824
#define DWE_ (D_ + W_ + E_) // 3336

// ---------------------------------------------------------------------------
// Scratch
// ---------------------------------------------------------------------------
struct Scratch {
    float havg[B_ * E_];
    float skpA[2][3][B_ * D_];
    float skpB[2][3][B_ * D_];
    float spart[3 * S_ * B_];
    float beta[B_];
    float ctx[B_ * E_];
    float x[B_ * WE_];
    float z[B_ * DWE_];
    float gp0[B_ * 4 * D_];
    float gp1[B_ * 4 * D_];
    int   amax[B_];
    __half h16[S_ * B_ * E_];   // fp16 copy of h
    __half w16[D_ * E_];        // fp16 copy of Wa1[:, D:]
};
__device__ Scratch g_s;

// ---------------------------------------------------------------------------
// fp16 MMA helpers
// ---------------------------------------------------------------------------
__device__ __forceinline__ uint32_t packh2(float a, float b) {
    __half2 h = __floats2half2_rn(a, b);
    return *(uint32_t*)&h;
}
__device__ __forceinline__ void mma_f16(float (&c)[4], const uint32_t (&a)[4],
                                        const uint32_t b0, const uint32_t b1) {
    asm volatile(
        "mma.sync.aligned.m16n8k16.row.col.f32.f16.f16.f32 "
        "{%0,%1,%2,%3},{%4,%5,%6,%7},{%8,%9},{%0,%1,%2,%3};"
        : "+f"(c[0]), "+f"(c[1]), "+f"(c[2]), "+f"(c[3])
        : "r"(a[0]), "r"(a[1]), "r"(a[2]), "r"(a[3]), "r"(b0), "r"(b1));
}
__device__ __forceinline__ void ldsm4(uint32_t (&r)[4], uint32_t addr) {
    asm volatile("ldmatrix.sync.aligned.m8n8.x4.shared.b16 {%0,%1,%2,%3}, [%4];"
        : "=r"(r[0]), "=r"(r[1]), "=r"(r[2]), "=r"(r[3]) : "r"(addr));
}
__device__ __forceinline__ void ldsm2(uint32_t (&r)[2], uint32_t addr) {
    asm volatile("ldmatrix.sync.aligned.m8n8.x2.shared.b16 {%0,%1}, [%2];"
        : "=r"(r[0]), "=r"(r[1]) : "r"(addr));
}
__device__ __forceinline__ void ld8(float* d, const float* p) {
    float4 a = ((const float4*)p)[0], b = ((const float4*)p)[1];
    d[0]=a.x; d[1]=a.y; d[2]=a.z; d[3]=a.w; d[4]=b.x; d[5]=b.y; d[6]=b.z; d[7]=b.w;
}
__device__ __forceinline__ void add8(float* d, const float* p) {
    float4 a = ((const float4*)p)[0], b = ((const float4*)p)[1];
    d[0]+=a.x; d[1]+=a.y; d[2]+=a.z; d[3]+=a.w; d[4]+=b.x; d[5]+=b.y; d[6]+=b.z; d[7]+=b.w;
}

// Row stride 20 uint32: 8-row base pattern {0,20,8,28,16,4,24,12} mod 32 ->
// conflict-free LDSM row fetches and STS.128 phases.
#define SPADH 20

// ---------------------------------------------------------------------------
// fp32 -> fp16 preconversion: h16 = h, w16 = Wa1[:, D:] (row stride E)
// ---------------------------------------------------------------------------
__global__ __launch_bounds__(256) void conv16_kernel(
    const float* __restrict__ h, const float* __restrict__ Wa1,
    __half* __restrict__ h16, __half* __restrict__ w16)
{
    const int HT = S_ * B_ * E_ / 8;       // octets in h
    const int WT = D_ * E_ / 8;            // octets in w16
    int idx = blockIdx.x * 256 + threadIdx.x;
    if (idx < HT) {
        const float4* p = (const float4*)(h + (size_t)idx * 8);
        float4 a = p[0], b = p[1];
        *(uint4*)(h16 + (size_t)idx * 8) =
            make_uint4(packh2(a.x, a.y), packh2(a.z, a.w),
                       packh2(b.x, b.y), packh2(b.z, b.w));
    } else if (idx - HT < WT) {
        int j = idx - HT;
        int n = j / (E_ / 8), k8 = j % (E_ / 8);
        const float4* p = (const float4*)(Wa1 + (size_t)n * DE_ + D_ + k8 * 8);
        float4 a = p[0], b = p[1];
        *(uint4*)(w16 + (size_t)n * E_ + k8 * 8) =
            make_uint4(packh2(a.x, a.y), packh2(a.z, a.w),
                       packh2(b.x, b.y), packh2(b.z, b.w));
    }
}

// ---------------------------------------------------------------------------
// Small-GEMM K-segment, fp16 MMA, fused A-side reduce (unchanged from R8)
// ---------------------------------------------------------------------------
struct SKJob {
    const float* A0; const float* A1p; const float* A2p;
    const float* kb; int krelu;
    const float* W; int K; int ldw; int N; float* Cpart;
};
struct SKJob2 { SKJob j[2]; };

template<int BN>
__device__ __forceinline__ void seg64(
    const SKJob& j, const int nb, const int t0, const int t1,
    uint32_t As[64][SPADH], uint32_t Ws[BN][SPADH],
    float (&acc)[2][BN / 32][4])
{
    constexpr int NF  = BN / 32;
    constexpr int WPT = (BN == 64) ? 8 : 16;
    const int tid  = threadIdx.x;
    const int lane = tid & 31, wid = tid >> 5;
    const int warpM = wid >> 2, warpN = wid & 3;

    const int am  = tid & 63, akg = (tid >> 6) * 8;
    const int wn  = (BN == 64) ? (tid & 63) : (tid & 127);
    const int wkg = (BN == 64) ? ((tid >> 6) * 8) : ((tid >> 7) * 16);
    const bool wvalid = (nb + wn) < j.N;
    const int K = j.K;
    const float* A0r = j.A0 + (size_t)am * K;
    const float* A1r = j.A1p ? j.A1p + (size_t)am * K : nullptr;
    const float* A2r = j.A2p ? j.A2p + (size_t)am * K : nullptr;
    const float* Wbase = j.W + (size_t)(nb + wn) * j.ldw;

    uint32_t aAddr[2][2], bAddr[NF];
    #pragma unroll
    for (int mf = 0; mf < 2; mf++)
        #pragma unroll
        for (int ks = 0; ks < 2; ks++)
            aAddr[mf][ks] = (uint32_t)__cvta_generic_to_shared(
                &As[warpM * 32 + mf * 16 + (lane & 15)][ks * 8 + 4 * (lane >> 4)]);
    #pragma unroll
    for (int nf = 0; nf < NF; nf++)
        bAddr[nf] = (uint32_t)__cvta_generic_to_shared(
            &Ws[warpN * (BN / 4) + nf * 8 + (lane & 7)][4 * (lane >> 3)]);

    float ra[8], rw[WPT];

    auto loadA = [&](int ti) {
        const int k0 = ti * 32 + akg;
        if (k0 + 8 <= K) {
            ld8(ra, A0r + k0);
            if (A1r) add8(ra, A1r + k0);
            if (A2r) add8(ra, A2r + k0);
            if (j.kb) add8(ra, j.kb + k0);
        } else {
            #pragma unroll
            for (int i = 0; i < 8; i++) {
                int k = k0 + i; float v = 0.f;
                if (k < K) {
                    v = A0r[k];
                    if (A1r) v += A1r[k];
                    if (A2r) v += A2r[k];
                    if (j.kb) v += j.kb[k];
                }
                ra[i] = v;
            }
        }
        if (j.krelu) {
            #pragma unroll
            for (int i = 0; i < 8; i++) ra[i] = fmaxf(ra[i], 0.f);
        }
    };
    auto loadW = [&](int ti) {
        const int k0 = ti * 32 + wkg;
        if (wvalid && k0 + WPT <= K) {
            #pragma unroll
            for (int i = 0; i < WPT / 4; i++) {
                float4 v = *(const float4*)(Wbase + k0 + i * 4);
                rw[i*4+0]=v.x; rw[i*4+1]=v.y; rw[i*4+2]=v.z; rw[i*4+3]=v.w;
            }
        } else {
            #pragma unroll
            for (int i = 0; i < WPT; i++)
                rw[i] = (wvalid && (k0 + i) < K) ? Wbase[k0 + i] : 0.f;
        }
    };

    loadA(t0);
    loadW(t0);

    for (int ti = t0; ti < t1; ti++) {
        __syncthreads();
        *(uint4*)&As[am][akg >> 1] =
            make_uint4(packh2(ra[0], ra[1]), packh2(ra[2], ra[3]),
                       packh2(ra[4], ra[5]), packh2(ra[6], ra[7]));
        #pragma unroll
        for (int h8 = 0; h8 < WPT / 8; h8++) {
            const float* r = rw + h8 * 8;
            *(uint4*)&Ws[wn][(wkg >> 1) + h8 * 4] =
                make_uint4(packh2(r[0], r[1]), packh2(r[2], r[3]),
                           packh2(r[4], r[5]), packh2(r[6], r[7]));
        }
        __syncthreads();

        if (ti + 1 < t1) { loadA(ti + 1); loadW(ti + 1); }

        uint32_t b[NF][4];
        #pragma unroll
        for (int nf = 0; nf < NF; nf++) ldsm4(b[nf], bAddr[nf]);
        #pragma unroll
        for (int ks = 0; ks < 2; ks++) {
            uint32_t a[2][4];
            ldsm4(a[0], aAddr[0][ks]);
            ldsm4(a[1], aAddr[1][ks]);
            #pragma unroll
            for (int nf = 0; nf < NF; nf++) {
                mma_f16(acc[0][nf], a[0], b[nf][2 * ks], b[nf][2 * ks + 1]);
                mma_f16(acc[1][nf], a[1], b[nf][2 * ks], b[nf][2 * ks + 1]);
            }
        }
    }
}

template<int BN>
__global__ __launch_bounds__(256) void sk_gemm_kernel(SKJob2 jobs)
{
    constexpr int NF = BN / 32;
    __shared__ __align__(16) uint32_t As[64][SPADH];
    __shared__ __align__(16) uint32_t Ws[BN][SPADH];

    const SKJob j = jobs.j[blockIdx.y];
    const int nb = blockIdx.x * BN;
    if (nb >= j.N) return;

    const int tiles = (j.K + 31) >> 5;
    const int KS = gridDim.z, kz = blockIdx.z;
    const int tpk = (tiles + KS - 1) / KS;
    const int t0 = kz * tpk;
    const int t1 = (t0 + tpk < tiles) ? (t0 + tpk) : tiles;

    float acc[2][NF][4] = {};
    if (t0 < t1)
        seg64<BN>(j, nb, t0, t1, As, Ws, acc);

    float* C = j.Cpart + (size_t)kz * 64 * j.N;
    const int tid = threadIdx.x, lane = tid & 31, wid = tid >> 5;
    const int warpM = wid >> 2, warpN = wid & 3;
    const int g = lane >> 2, t = lane & 3;

    #pragma unroll
    for (int mf = 0; mf < 2; mf++) {
        const int row = warpM * 32 + mf * 16 + g;
        #pragma unroll
        for (int nf = 0; nf < NF; nf++) {
            const int col = nb + warpN * (BN / 4) + nf * 8 + 2 * t;
            if (col < j.N) {
                *(float2*)&C[(size_t)row * j.N + col]       = make_float2(acc[mf][nf][0], acc[mf][nf][1]);
                *(float2*)&C[(size_t)(row + 8) * j.N + col] = make_float2(acc[mf][nf][2], acc[mf][nf][3]);
            }
        }
    }
}

__global__ __launch_bounds__(256) void logits_kernel(
    const float* __restrict__ z, const float* __restrict__ Wt,
    const float* __restrict__ bias, float* __restrict__ C)
{
    __shared__ __align__(16) uint32_t As[64][SPADH];
    __shared__ __align__(16) uint32_t Ws[128][SPADH];

    SKJob j; j.A0 = z; j.A1p = nullptr; j.A2p = nullptr; j.kb = nullptr; j.krelu = 0;
    j.W = Wt; j.K = DWE_; j.ldw = DWE_; j.N = V_; j.Cpart = nullptr;
    const int nb = blockIdx.x * 128;

    float acc[2][4][4] = {};
    seg64<128>(j, nb, 0, (DWE_ + 31) >> 5, As, Ws, acc);

    const int tid = threadIdx.x, lane = tid & 31, wid = tid >> 5;
    const int warpM = wid >> 2, warpN = wid & 3;
    const int g = lane >> 2, t = lane & 3;

    #pragma unroll
    for (int mf = 0; mf < 2; mf++) {
        const int row = warpM * 32 + mf * 16 + g;
        #pragma unroll
        for (int nf = 0; nf < 4; nf++) {
            const int col = nb + warpN * 32 + nf * 8 + 2 * t;
            float b0 = bias[col], b1 = bias[col + 1];
            *(float2*)&C[(size_t)row * V_ + col]       = make_float2(acc[mf][nf][0] + b0, acc[mf][nf][1] + b1);
            *(float2*)&C[(size_t)(row + 8) * V_ + col] = make_float2(acc[mf][nf][2] + b0, acc[mf][nf][3] + b1);
        }
    }
}

// ---------------------------------------------------------------------------
// Fused attention scores v2: preconverted fp16 inputs, ktile=32, ping-pong
// dynamic smem (1 sync/iter), fused qpart partial reduce in epilogue.
// BM=256 (4 seq), BN=128, 8 warps (4M x 2N), warp tile 64x64. grid = (49, 3).
// ---------------------------------------------------------------------------
#define SPH2 20
#define AS_WORDS (256 * SPH2)
#define WS_WORDS (128 * SPH2)
#define SC_DYN ((2 * AS_WORDS + 2 * WS_WORDS) * 4)   // 61440 B

__global__ __launch_bounds__(256, 1) void mma_scores_kernel(
    const __half* __restrict__ h16, const __half* __restrict__ w16,
    const float* __restrict__ qp0, const float* __restrict__ qp1,
    const float* __restrict__ qp2, const float* __restrict__ ba1,
    const float* __restrict__ Wa2, float* __restrict__ spart)
{
    extern __shared__ uint32_t dyn[];
    uint32_t (*As)[256][SPH2] = (uint32_t(*)[256][SPH2])dyn;
    uint32_t (*Ws)[128][SPH2] = (uint32_t(*)[128][SPH2])(dyn + 2 * AS_WORDS);

    const int tid = threadIdx.x, lane = tid & 31, wid = tid >> 5;
    const int warpM = wid >> 1, warpN = wid & 1;
    const int g = lane >> 2, t = lane & 3;

    const __half* Abase = h16 + ((size_t)blockIdx.x * 256 + tid) * E_;
    const int wrow = tid & 127;
    const bool wldr = (tid < 128);

    const uint32_t ASO = AS_WORDS * 4, WSO = WS_WORDS * 4;
    uint32_t aA[4], bA[8];
    #pragma unroll
    for (int mf = 0; mf < 4; mf++)
        aA[mf] = (uint32_t)__cvta_generic_to_shared(
            &As[0][warpM * 64 + mf * 16 + (lane & 15)][4 * (lane >> 4)]);
    #pragma unroll
    for (int nf = 0; nf < 8; nf++)
        bA[nf] = (uint32_t)__cvta_generic_to_shared(
            &Ws[0][warpN * 64 + nf * 8 + (lane & 7)][4 * ((lane >> 3) & 1)]);

    float sacc[4][2] = {};

    const int tile0 = blockIdx.y * 5;
    for (int tile = tile0; tile < tile0 + 5; tile++) {
        const int nb = tile * 128;
        const bool wv = wldr && (nb + wrow) < D_;
        const __half* Wbase = w16 + (size_t)(nb + wrow) * E_;

        uint4 ra[4], rw[4];
        float acc[4][8][4] = {};

        auto loadA = [&](int ti) {
            const uint4* p = (const uint4*)(Abase + ti * 32);
            ra[0] = p[0]; ra[1] = p[1]; ra[2] = p[2]; ra[3] = p[3];
        };
        auto loadW = [&](int ti) {
            if (wv) {
                const uint4* p = (const uint4*)(Wbase + ti * 32);
                rw[0] = p[0]; rw[1] = p[1]; rw[2] = p[2]; rw[3] = p[3];
            } else if (wldr) {
                rw[0] = rw[1] = rw[2] = rw[3] = make_uint4(0, 0, 0, 0);
            }
        };
        auto stsAB = [&](int buf) {
            uint4* pa = (uint4*)&As[buf][tid][0];
            pa[0] = ra[0]; pa[1] = ra[1]; pa[2] = ra[2]; pa[3] = ra[3];
            if (wldr) {
                uint4* pw = (uint4*)&Ws[buf][wrow][0];
                pw[0] = rw[0]; pw[1] = rw[1]; pw[2] = rw[2]; pw[3] = rw[3];
            }
        };
        auto domma = [&](int buf) {
            const uint32_t ao = buf * ASO, wo = buf * WSO;
            #pragma unroll
            for (int ks = 0; ks < 2; ks++) {
                uint32_t b[8][2];
                #pragma unroll
                for (int nf = 0; nf < 8; nf++) ldsm2(b[nf], bA[nf] + wo + ks * 32);
                #pragma unroll
                for (int mf = 0; mf < 4; mf++) {
                    uint32_t a[4];
                    ldsm4(a, aA[mf] + ao + ks * 32);
                    #pragma unroll
                    for (int nf = 0; nf < 8; nf++)
                        mma_f16(acc[mf][nf], a, b[nf][0], b[nf][1]);
                }
            }
        };

        loadA(0); loadW(0);
        __syncthreads();
        stsAB(0);
        loadA(1); loadW(1);

        for (int ti = 0; ti < E_ / 32; ti++) {
            __syncthreads();
            if (ti + 1 < E_ / 32) stsAB((ti + 1) & 1);
            if (ti + 2 < E_ / 32) { loadA(ti + 2); loadW(ti + 2); }
            domma(ti & 1);
        }

        // epilogue: + (qp0+qp1+qp2+ba1), relu, * Wa2, accumulate per-row
        #pragma unroll
        for (int mf = 0; mf < 4; mf++) {
            const int r0 = warpM * 64 + mf * 16 + g;
            const int b0 = r0 & 63, b1 = (r0 + 8) & 63;
            #pragma unroll
            for (int nf = 0; nf < 8; nf++) {
                const int col = nb + warpN * 64 + nf * 8 + 2 * t;
                if (col < D_) {
                    float2 w  = *(const float2*)(Wa2 + col);
                    float2 bb = *(const float2*)(ba1 + col);
                    size_t i0 = (size_t)b0 * D_ + col, i1 = (size_t)b1 * D_ + col;
                    float2 a0 = *(const float2*)(qp0 + i0);
                    float2 a1v = *(const float2*)(qp1 + i0);
                    float2 a2 = *(const float2*)(qp2 + i0);
                    float2 c0 = *(const float2*)(qp0 + i1);
                    float2 c1 = *(const float2*)(qp1 + i1);
                    float2 c2 = *(const float2*)(qp2 + i1);
                    float q0x = bb.x + a0.x + a1v.x + a2.x;
                    float q0y = bb.y + a0.y + a1v.y + a2.y;
                    float q1x = bb.x + c0.x + c1.x + c2.x;
                    float q1y = bb.y + c0.y + c1.y + c2.y;
                    sacc[mf][0] += fmaxf(acc[mf][nf][0] + q0x, 0.f) * w.x
                                 + fmaxf(acc[mf][nf][1] + q0y, 0.f) * w.y;
                    sacc[mf][1] += fmaxf(acc[mf][nf][2] + q1x, 0.f) * w.x
                                 + fmaxf(acc[mf][nf][3] + q1y, 0.f) * w.y;
                }
            }
        }
    }

    __syncthreads();
    float* red = (float*)dyn;        // [256][9] overlay
    #pragma unroll
    for (int mf = 0; mf < 4; mf++) {
        const int r0 = warpM * 64 + mf * 16 + g;
        red[r0 * 9 + warpN * 4 + t]       = sacc[mf][0];
        red[(r0 + 8) * 9 + warpN * 4 + t] = sacc[mf][1];
    }
    __syncthreads();
    {
        const int row = tid;
        float a = 0.f;
        #pragma unroll
        for (int c = 0; c < 8; c++) a += red[row * 9 + c];
        const int s = blockIdx.x * 4 + (row >> 6);
        const int b = row & 63;
        spart[(size_t)blockIdx.y * S_ * B_ + (size_t)s * B_ + b] = a;
    }
}

// ---------------------------------------------------------------------------
// Small kernels (unchanged)
// ---------------------------------------------------------------------------
__global__ void havg_kernel(const float* __restrict__ h, float* __restrict__ havg)
{
    int b = blockIdx.x;
    int e = blockIdx.y * 256 + threadIdx.x;
    float s = 0.f;
    for (int si = 0; si < S_; si++)
        s += h[((size_t)si * B_ + b) * E_ + e];
    havg[(size_t)b * E_ + e] = s * (1.f / (float)S_);
}

__global__ __launch_bounds__(256) void softmax_beta_kernel(
    const float* __restrict__ spart,
    const float* __restrict__ hp0, const float* __restrict__ hp1,
    const float* __restrict__ hp2, const float* __restrict__ bh2,
    const float* __restrict__ Wb, const float* __restrict__ bb,
    const float* __restrict__ ba2,
    float* __restrict__ aw_out, float* __restrict__ beta)
{
    int b = blockIdx.x, tid = threadIdx.x;
    __shared__ float sm[256];

    float p = 0.f;
    for (int d = tid; d < D_; d += 256) {
        size_t i = (size_t)b * D_ + d;
        float hv = hp0[i] + hp1[i] + hp2[i] + bh2[d];
        p = fmaf(hv, Wb[d], p);
    }
    sm[tid] = p; __syncthreads();
    for (int o = 128; o > 0; o >>= 1) { if (tid < o) sm[tid] += sm[tid + o]; __syncthreads(); }
    if (tid == 0) beta[b] = 1.f / (1.f + expf(-(sm[0] + bb[0])));
    __syncthreads();

    float v = -3.4e38f;
    if (tid < S_) {
        size_t idx = (size_t)tid * B_ + b;
        v = spart[idx] + spart[(size_t)S_ * B_ + idx] + spart[2 * (size_t)S_ * B_ + idx] + ba2[0];
    }
    sm[tid] = v; __syncthreads();
    for (int o = 128; o > 0; o >>= 1) { if (tid < o) sm[tid] = fmaxf(sm[tid], sm[tid + o]); __syncthreads(); }
    float mx = sm[0]; __syncthreads();
    float e = (tid < S_) ? expf(v - mx) : 0.f;
    sm[tid] = e; __syncthreads();
    for (int o = 128; o > 0; o >>= 1) { if (tid < o) sm[tid] += sm[tid + o]; __syncthreads(); }
    float inv = 1.f / sm[0];
    if (tid < S_) aw_out[(size_t)tid * B_ + b] = e * inv;
}

__global__ void ctx_kernel(const float* __restrict__ h, const float* __restrict__ aw,
                           const float* __restrict__ beta, float* __restrict__ ctx)
{
    int b = blockIdx.x;
    int e = blockIdx.y * 256 + threadIdx.x;
    float s = 0.f;
    for (int si = 0; si < S_; si++)
        s = fmaf(aw[(size_t)si * B_ + b], h[((size_t)si * B_ + b) * E_ + e], s);
    ctx[(size_t)b * E_ + e] = s * beta[b];
}

__global__ __launch_bounds__(256) void argmax_kernel(const float* __restrict__ y, int* __restrict__ amax)
{
    int b = blockIdx.x, tid = threadIdx.x;
    float bm = -3.4e38f; int bi = 0;
    for (int i = tid; i < V_; i += 256) {
        float v = y[(size_t)b * V_ + i];
        if (v > bm) { bm = v; bi = i; }
    }
    __shared__ float sv[256];
    __shared__ int si_[256];
    sv[tid] = bm; si_[tid] = bi; __syncthreads();
    for (int o = 128; o > 0; o >>= 1) {
        if (tid < o) {
            if (sv[tid + o] > sv[tid] || (sv[tid + o] == sv[tid] && si_[tid + o] < si_[tid])) {
                sv[tid] = sv[tid + o]; si_[tid] = si_[tid + o];
            }
        }
        __syncthreads();
    }
    if (tid == 0) amax[b] = si_[0];
}

__global__ void xbuild_kernel(const float* __restrict__ emb, const int* __restrict__ Etm1,
                              const float* __restrict__ ctx, float* __restrict__ x)
{
    int b = blockIdx.x;
    int i = blockIdx.y * 256 + threadIdx.x;
    if (i < W_) x[(size_t)b * WE_ + i] = emb[(size_t)Etm1[b] * W_ + i];
    else        x[(size_t)b * WE_ + i] = ctx[(size_t)b * E_ + (i - W_)];
}

__global__ void lstm_kernel(const float* __restrict__ gp0, const float* __restrict__ gp1,
                            const float* __restrict__ b_ih, const float* __restrict__ b_hh,
                            const float* __restrict__ cp0, const float* __restrict__ cp1,
                            const float* __restrict__ cp2, const float* __restrict__ bc2,
                            float* __restrict__ out, float* __restrict__ z)
{
    int b = blockIdx.x;
    int d = blockIdx.y * 256 + threadIdx.x;
    if (d >= D_) return;
    const size_t base = (size_t)b * 4 * D_;
    float gi = gp0[base + d]          + gp1[base + d]          + b_ih[d]          + b_hh[d];
    float gf = gp0[base + D_ + d]     + gp1[base + D_ + d]     + b_ih[D_ + d]     + b_hh[D_ + d];
    float gg = gp0[base + 2*D_ + d]   + gp1[base + 2*D_ + d]   + b_ih[2*D_ + d]   + b_hh[2*D_ + d];
    float go = gp0[base + 3*D_ + d]   + gp1[base + 3*D_ + d]   + b_ih[3*D_ + d]   + b_hh[3*D_ + d];
    size_t ci = (size_t)b * D_ + d;
    float c0 = cp0[ci] + cp1[ci] + cp2[ci] + bc2[d];
    float ig = 1.f / (1.f + expf(-gi));
    float fg = 1.f / (1.f + expf(-gf));
    float gt = tanhf(gg);
    float og = 1.f / (1.f + expf(-go));
    float c = fmaf(fg, c0, ig * gt);
    float ht = og * tanhf(c);
    out[(size_t)B_ * V_ + (size_t)b * D_ + d] = ht;
    out[(size_t)B_ * V_ + (size_t)B_ * D_ + (size_t)b * D_ + d] = c;
    z[(size_t)b * DWE_ + d] = ht;
}

__global__ void zbuild_kernel(const float* __restrict__ emb, const int* __restrict__ amax,
                              const float* __restrict__ ctx, float* __restrict__ z)
{
    int b = blockIdx.x;
    int i = blockIdx.y * 256 + threadIdx.x;
    if (i < W_) z[(size_t)b * DWE_ + D_ + i] = emb[(size_t)amax[b] * W_ + i];
    else        z[(size_t)b * DWE_ + D_ + i] = ctx[(size_t)b * E_ + (i - W_)];
}

// ---------------------------------------------------------------------------
// Launch
// ---------------------------------------------------------------------------
extern "C" void kernel_launch(void* const* d_in, const int* in_sizes, int n_in,
                              void* d_out, int out_size)
{
    const int*   E_tm1 = (const int*)d_in[0];
    const float* y_tm1 = (const float*)d_in[1];
    const float* h     = (const float*)d_in[2];
    const float* emb   = (const float*)d_in[3];
    const float* W_ih  = (const float*)d_in[4];
    const float* b_ih  = (const float*)d_in[5];
    const float* W_hh  = (const float*)d_in[6];
    const float* b_hh  = (const float*)d_in[7];
    const float* W_out = (const float*)d_in[8];
    const float* b_out = (const float*)d_in[9];
    const float* Wh1 = (const float*)d_in[10]; const float* bh1 = (const float*)d_in[11];
    const float* Wh2 = (const float*)d_in[12]; const float* bh2 = (const float*)d_in[13];
    const float* Wc1 = (const float*)d_in[14]; const float* bc1 = (const float*)d_in[15];
    const float* Wc2 = (const float*)d_in[16]; const float* bc2 = (const float*)d_in[17];
    const float* Wa1 = (const float*)d_in[18]; const float* ba1 = (const float*)d_in[19];
    const float* Wa2 = (const float*)d_in[20]; const float* ba2 = (const float*)d_in[21];
    const float* Wb  = (const float*)d_in[22]; const float* bb  = (const float*)d_in[23];
    float* out = (float*)d_out;

    Scratch* s = nullptr;
    cudaGetSymbolAddress((void**)&s, g_s);

    cudaFuncSetAttribute(mma_scores_kernel,
                         cudaFuncAttributeMaxDynamicSharedMemorySize, SC_DYN);

    const int GN_D  = (D_ + 63) / 64;            // 29
    const int GN_4D = (4 * D_ + 127) / 128;      // 57
    const int GN_V  = V_ / 128;                  // 250
    const int CONV_BLK = (S_ * B_ * E_ / 8 + D_ * E_ / 8 + 255) / 256;  // 7172

    // 0. fp16 preconversion of h and Wa1 key-slice
    conv16_kernel<<<CONV_BLK, 256>>>(h, Wa1, s->h16, s->w16);

    // 1. encoder mean
    havg_kernel<<<dim3(B_, E_ / 256), 256>>>(h, s->havg);

    // 2. init-state layer1 -> partials (KS=2)
    {
        SKJob2 jj;
        jj.j[0] = {s->havg, nullptr, nullptr, nullptr, 0, Wh1, E_, E_, D_, s->skpA[0][0]};
        jj.j[1] = {s->havg, nullptr, nullptr, nullptr, 0, Wc1, E_, E_, D_, s->skpA[1][0]};
        sk_gemm_kernel<64><<<dim3(GN_D, 2, 2), 256>>>(jj);
    }
    // 3. layer2, A = relu(sum L1 partials + b1) fused (KS=3)
    {
        SKJob2 jj;
        jj.j[0] = {s->skpA[0][0], s->skpA[0][1], nullptr, bh1, 1, Wh2, D_, D_, D_, s->skpB[0][0]};
        jj.j[1] = {s->skpA[1][0], s->skpA[1][1], nullptr, bc1, 1, Wc2, D_, D_, D_, s->skpB[1][0]};
        sk_gemm_kernel<64><<<dim3(GN_D, 2, 3), 256>>>(jj);
    }
    // 4. qpart partials = (h0 = sum L2 partials + bh2) @ Wa1[:, :D]^T  (KS=3)
    {
        SKJob2 jj;
        jj.j[0] = {s->skpB[0][0], s->skpB[0][1], s->skpB[0][2], bh2, 0, Wa1, D_, DE_, D_, s->skpA[0][0]};
        jj.j[1] = jj.j[0];
        sk_gemm_kernel<64><<<dim3(GN_D, 1, 3), 256>>>(jj);
    }

    // 5. fused scores GEMM (fp16, preconverted; qpart reduce fused in epilogue)
    mma_scores_kernel<<<dim3(S_ / 4, 3), 256, SC_DYN>>>(
        s->h16, s->w16,
        s->skpA[0][0], s->skpA[0][0] + (size_t)B_ * D_, s->skpA[0][0] + 2 * (size_t)B_ * D_,
        ba1, Wa2, s->spart);

    // 6. argmax of y_tm1
    argmax_kernel<<<B_, 256>>>(y_tm1, s->amax);

    // 7. softmax + beta (h0 virtual from partials)
    float* aw_out = out + (size_t)B_ * V_ + 2 * (size_t)B_ * D_;
    softmax_beta_kernel<<<B_, 256>>>(s->spart, s->skpB[0][0], s->skpB[0][1], s->skpB[0][2],
                                     bh2, Wb, bb, ba2, aw_out, s->beta);

    // 8. context
    ctx_kernel<<<dim3(B_, E_ / 256), 256>>>(h, aw_out, s->beta, s->ctx);

    // 9. LSTM input + gates (h0 virtual in job1)
    xbuild_kernel<<<dim3(B_, WE_ / 256), 256>>>(emb, E_tm1, s->ctx, s->x);
    {
        SKJob2 jj;
        jj.j[0] = {s->x, nullptr, nullptr, nullptr, 0, W_ih, WE_, WE_, 4 * D_, s->gp0};
        jj.j[1] = {s->skpB[0][0], s->skpB[0][1], s->skpB[0][2], bh2, 0, W_hh, D_, D_, 4 * D_, s->gp1};
        sk_gemm_kernel<128><<<dim3(GN_4D, 2, 1), 256>>>(jj);
    }

    // 10. LSTM pointwise (c0 virtual from partials)
    lstm_kernel<<<dim3(B_, (D_ + 255) / 256), 256>>>(
        s->gp0, s->gp1, b_ih, b_hh,
        s->skpB[1][0], s->skpB[1][1], s->skpB[1][2], bc2, out, s->z);

    // 11. z tail
    zbuild_kernel<<<dim3(B_, WE_ / 256), 256>>>(emb, s->amax, s->ctx, s->z);

    // 12. logits
    logits_kernel<<<GN_V, 256>>>(s->z, W_out, b_out, out);
}

// round 10
// speedup vs baseline: 1.0037x; 1.0037x over previous
#include <cuda_runtime.h>
#include <cuda_fp16.h>
#include <math.h>
#include <stdint.h>

#define S_ 196
#define B_ 64
#define E_ 1024
#define D_ 1800
#define W_ 512
#define V_ 32000
#define WE_ (W_ + E_)       // 1536
#define DE_ (D_ + E_)       // 2824
#define DWE_ (D_ + W_ + E_) // 3336

// ---------------------------------------------------------------------------
// Scratch
// ---------------------------------------------------------------------------
struct Scratch {
    float havg[B_ * E_];
    float skpA[2][3][B_ * D_];
    float skpB[2][3][B_ * D_];
    float spart[3 * S_ * B_];
    float beta[B_];
    float ctx[B_ * E_];
    float x[B_ * WE_];
    float z[B_ * DWE_];
    float gp0[B_ * 4 * D_];
    float gp1[B_ * 4 * D_];
    int   amax[B_];
    __half h16[S_ * B_ * E_];   // fp16 copy of h
    __half w16[D_ * E_];        // fp16 copy of Wa1[:, D:]
};
__device__ Scratch g_s;

// ---------------------------------------------------------------------------
// fp16 MMA helpers
// ---------------------------------------------------------------------------
__device__ __forceinline__ uint32_t packh2(float a, float b) {
    __half2 h = __floats2half2_rn(a, b);
    return *(uint32_t*)&h;
}
__device__ __forceinline__ void mma_f16(float (&c)[4], const uint32_t (&a)[4],
                                        const uint32_t b0, const uint32_t b1) {
    asm volatile(
        "mma.sync.aligned.m16n8k16.row.col.f32.f16.f16.f32 "
        "{%0,%1,%2,%3},{%4,%5,%6,%7},{%8,%9},{%0,%1,%2,%3};"
        : "+f"(c[0]), "+f"(c[1]), "+f"(c[2]), "+f"(c[3])
        : "r"(a[0]), "r"(a[1]), "r"(a[2]), "r"(a[3]), "r"(b0), "r"(b1));
}
__device__ __forceinline__ void ldsm4(uint32_t (&r)[4], uint32_t addr) {
    asm volatile("ldmatrix.sync.aligned.m8n8.x4.shared.b16 {%0,%1,%2,%3}, [%4];"
        : "=r"(r[0]), "=r"(r[1]), "=r"(r[2]), "=r"(r[3]) : "r"(addr));
}
__device__ __forceinline__ void ldsm2(uint32_t (&r)[2], uint32_t addr) {
    asm volatile("ldmatrix.sync.aligned.m8n8.x2.shared.b16 {%0,%1}, [%2];"
        : "=r"(r[0]), "=r"(r[1]) : "r"(addr));
}
__device__ __forceinline__ void ld8(float* d, const float* p) {
    float4 a = ((const float4*)p)[0], b = ((const float4*)p)[1];
    d[0]=a.x; d[1]=a.y; d[2]=a.z; d[3]=a.w; d[4]=b.x; d[5]=b.y; d[6]=b.z; d[7]=b.w;
}
__device__ __forceinline__ void add8(float* d, const float* p) {
    float4 a = ((const float4*)p)[0], b = ((const float4*)p)[1];
    d[0]+=a.x; d[1]+=a.y; d[2]+=a.z; d[3]+=a.w; d[4]+=b.x; d[5]+=b.y; d[6]+=b.z; d[7]+=b.w;
}

// Row stride 20 uint32: 8-row base pattern {0,20,8,28,16,4,24,12} mod 32 ->
// conflict-free LDSM row fetches and STS.128 phases.
#define SPADH 20

// ---------------------------------------------------------------------------
// fp32 -> fp16 preconversion: h16 = h, w16 = Wa1[:, D:] (row stride E)
// ---------------------------------------------------------------------------
__global__ __launch_bounds__(256) void conv16_kernel(
    const float* __restrict__ h, const float* __restrict__ Wa1,
    __half* __restrict__ h16, __half* __restrict__ w16)
{
    const int HT = S_ * B_ * E_ / 8;       // octets in h
    const int WT = D_ * E_ / 8;            // octets in w16
    int idx = blockIdx.x * 256 + threadIdx.x;
    if (idx < HT) {
        const float4* p = (const float4*)(h + (size_t)idx * 8);
        float4 a = p[0], b = p[1];
        *(uint4*)(h16 + (size_t)idx * 8) =
            make_uint4(packh2(a.x, a.y), packh2(a.z, a.w),
                       packh2(b.x, b.y), packh2(b.z, b.w));
    } else if (idx - HT < WT) {
        int j = idx - HT;
        int n = j / (E_ / 8), k8 = j % (E_ / 8);
        const float4* p = (const float4*)(Wa1 + (size_t)n * DE_ + D_ + k8 * 8);
        float4 a = p[0], b = p[1];
        *(uint4*)(w16 + (size_t)n * E_ + k8 * 8) =
            make_uint4(packh2(a.x, a.y), packh2(a.z, a.w),
                       packh2(b.x, b.y), packh2(b.z, b.w));
    }
}

// ---------------------------------------------------------------------------
// Small-GEMM K-segment, fp16 MMA, fused A-side reduce (unchanged from R8)
// ---------------------------------------------------------------------------
struct SKJob {
    const float* A0; const float* A1p; const float* A2p;
    const float* kb; int krelu;
    const float* W; int K; int ldw; int N; float* Cpart;
};
struct SKJob2 { SKJob j[2]; };

template<int BN>
__device__ __forceinline__ void seg64(
    const SKJob& j, const int nb, const int t0, const int t1,
    uint32_t As[64][SPADH], uint32_t Ws[BN][SPADH],
    float (&acc)[2][BN / 32][4])
{
    constexpr int NF  = BN / 32;
    constexpr int WPT = (BN == 64) ? 8 : 16;
    const int tid  = threadIdx.x;
    const int lane = tid & 31, wid = tid >> 5;
    const int warpM = wid >> 2, warpN = wid & 3;

    const int am  = tid & 63, akg = (tid >> 6) * 8;
    const int wn  = (BN == 64) ? (tid & 63) : (tid & 127);
    const int wkg = (BN == 64) ? ((tid >> 6) * 8) : ((tid >> 7) * 16);
    const bool wvalid = (nb + wn) < j.N;
    const int K = j.K;
    const float* A0r = j.A0 + (size_t)am * K;
    const float* A1r = j.A1p ? j.A1p + (size_t)am * K : nullptr;
    const float* A2r = j.A2p ? j.A2p + (size_t)am * K : nullptr;
    const float* Wbase = j.W + (size_t)(nb + wn) * j.ldw;

    uint32_t aAddr[2][2], bAddr[NF];
    #pragma unroll
    for (int mf = 0; mf < 2; mf++)
        #pragma unroll
        for (int ks = 0; ks < 2; ks++)
            aAddr[mf][ks] = (uint32_t)__cvta_generic_to_shared(
                &As[warpM * 32 + mf * 16 + (lane & 15)][ks * 8 + 4 * (lane >> 4)]);
    #pragma unroll
    for (int nf = 0; nf < NF; nf++)
        bAddr[nf] = (uint32_t)__cvta_generic_to_shared(
            &Ws[warpN * (BN / 4) + nf * 8 + (lane & 7)][4 * (lane >> 3)]);

    float ra[8], rw[WPT];

    auto loadA = [&](int ti) {
        const int k0 = ti * 32 + akg;
        if (k0 + 8 <= K) {
            ld8(ra, A0r + k0);
            if (A1r) add8(ra, A1r + k0);
            if (A2r) add8(ra, A2r + k0);
            if (j.kb) add8(ra, j.kb + k0);
        } else {
            #pragma unroll
            for (int i = 0; i < 8; i++) {
                int k = k0 + i; float v = 0.f;
                if (k < K) {
                    v = A0r[k];
                    if (A1r) v += A1r[k];
                    if (A2r) v += A2r[k];
                    if (j.kb) v += j.kb[k];
                }
                ra[i] = v;
            }
        }
        if (j.krelu) {
            #pragma unroll
            for (int i = 0; i < 8; i++) ra[i] = fmaxf(ra[i], 0.f);
        }
    };
    auto loadW = [&](int ti) {
        const int k0 = ti * 32 + wkg;
        if (wvalid && k0 + WPT <= K) {
            #pragma unroll
            for (int i = 0; i < WPT / 4; i++) {
                float4 v = *(const float4*)(Wbase + k0 + i * 4);
                rw[i*4+0]=v.x; rw[i*4+1]=v.y; rw[i*4+2]=v.z; rw[i*4+3]=v.w;
            }
        } else {
            #pragma unroll
            for (int i = 0; i < WPT; i++)
                rw[i] = (wvalid && (k0 + i) < K) ? Wbase[k0 + i] : 0.f;
        }
    };

    loadA(t0);
    loadW(t0);

    for (int ti = t0; ti < t1; ti++) {
        __syncthreads();
        *(uint4*)&As[am][akg >> 1] =
            make_uint4(packh2(ra[0], ra[1]), packh2(ra[2], ra[3]),
                       packh2(ra[4], ra[5]), packh2(ra[6], ra[7]));
        #pragma unroll
        for (int h8 = 0; h8 < WPT / 8; h8++) {
            const float* r = rw + h8 * 8;
            *(uint4*)&Ws[wn][(wkg >> 1) + h8 * 4] =
                make_uint4(packh2(r[0], r[1]), packh2(r[2], r[3]),
                           packh2(r[4], r[5]), packh2(r[6], r[7]));
        }
        __syncthreads();

        if (ti + 1 < t1) { loadA(ti + 1); loadW(ti + 1); }

        uint32_t b[NF][4];
        #pragma unroll
        for (int nf = 0; nf < NF; nf++) ldsm4(b[nf], bAddr[nf]);
        #pragma unroll
        for (int ks = 0; ks < 2; ks++) {
            uint32_t a[2][4];
            ldsm4(a[0], aAddr[0][ks]);
            ldsm4(a[1], aAddr[1][ks]);
            #pragma unroll
            for (int nf = 0; nf < NF; nf++) {
                mma_f16(acc[0][nf], a[0], b[nf][2 * ks], b[nf][2 * ks + 1]);
                mma_f16(acc[1][nf], a[1], b[nf][2 * ks], b[nf][2 * ks + 1]);
            }
        }
    }
}

template<int BN>
__global__ __launch_bounds__(256) void sk_gemm_kernel(SKJob2 jobs)
{
    constexpr int NF = BN / 32;
    __shared__ __align__(16) uint32_t As[64][SPADH];
    __shared__ __align__(16) uint32_t Ws[BN][SPADH];

    const SKJob j = jobs.j[blockIdx.y];
    const int nb = blockIdx.x * BN;
    if (nb >= j.N) return;

    const int tiles = (j.K + 31) >> 5;
    const int KS = gridDim.z, kz = blockIdx.z;
    const int tpk = (tiles + KS - 1) / KS;
    const int t0 = kz * tpk;
    const int t1 = (t0 + tpk < tiles) ? (t0 + tpk) : tiles;

    float acc[2][NF][4] = {};
    if (t0 < t1)
        seg64<BN>(j, nb, t0, t1, As, Ws, acc);

    float* C = j.Cpart + (size_t)kz * 64 * j.N;
    const int tid = threadIdx.x, lane = tid & 31, wid = tid >> 5;
    const int warpM = wid >> 2, warpN = wid & 3;
    const int g = lane >> 2, t = lane & 3;

    #pragma unroll
    for (int mf = 0; mf < 2; mf++) {
        const int row = warpM * 32 + mf * 16 + g;
        #pragma unroll
        for (int nf = 0; nf < NF; nf++) {
            const int col = nb + warpN * (BN / 4) + nf * 8 + 2 * t;
            if (col < j.N) {
                *(float2*)&C[(size_t)row * j.N + col]       = make_float2(acc[mf][nf][0], acc[mf][nf][1]);
                *(float2*)&C[(size_t)(row + 8) * j.N + col] = make_float2(acc[mf][nf][2], acc[mf][nf][3]);
            }
        }
    }
}

__global__ __launch_bounds__(256) void logits_kernel(
    const float* __restrict__ z, const float* __restrict__ Wt,
    const float* __restrict__ bias, float* __restrict__ C)
{
    __shared__ __align__(16) uint32_t As[64][SPADH];
    __shared__ __align__(16) uint32_t Ws[128][SPADH];

    SKJob j; j.A0 = z; j.A1p = nullptr; j.A2p = nullptr; j.kb = nullptr; j.krelu = 0;
    j.W = Wt; j.K = DWE_; j.ldw = DWE_; j.N = V_; j.Cpart = nullptr;
    const int nb = blockIdx.x * 128;

    float acc[2][4][4] = {};
    seg64<128>(j, nb, 0, (DWE_ + 31) >> 5, As, Ws, acc);

    const int tid = threadIdx.x, lane = tid & 31, wid = tid >> 5;
    const int warpM = wid >> 2, warpN = wid & 3;
    const int g = lane >> 2, t = lane & 3;

    #pragma unroll
    for (int mf = 0; mf < 2; mf++) {
        const int row = warpM * 32 + mf * 16 + g;
        #pragma unroll
        for (int nf = 0; nf < 4; nf++) {
            const int col = nb + warpN * 32 + nf * 8 + 2 * t;
            float b0 = bias[col], b1 = bias[col + 1];
            *(float2*)&C[(size_t)row * V_ + col]       = make_float2(acc[mf][nf][0] + b0, acc[mf][nf][1] + b1);
            *(float2*)&C[(size_t)(row + 8) * V_ + col] = make_float2(acc[mf][nf][2] + b0, acc[mf][nf][3] + b1);
        }
    }
}

// ---------------------------------------------------------------------------
// Fused attention scores v2: preconverted fp16 inputs, ktile=32, ping-pong
// dynamic smem (1 sync/iter), fused qpart partial reduce in epilogue.
// BM=256 (4 seq), BN=128, 8 warps (4M x 2N), warp tile 64x64. grid = (49, 3).
// ---------------------------------------------------------------------------
#define SPH2 20
#define AS_WORDS (256 * SPH2)
#define WS_WORDS (128 * SPH2)
#define SC_DYN ((2 * AS_WORDS + 2 * WS_WORDS) * 4)   // 61440 B

__global__ __launch_bounds__(256, 1) void mma_scores_kernel(
    const __half* __restrict__ h16, const __half* __restrict__ w16,
    const float* __restrict__ qp0, const float* __restrict__ qp1,
    const float* __restrict__ qp2, const float* __restrict__ ba1,
    const float* __restrict__ Wa2, float* __restrict__ spart)
{
    extern __shared__ uint32_t dyn[];
    uint32_t (*As)[256][SPH2] = (uint32_t(*)[256][SPH2])dyn;
    uint32_t (*Ws)[128][SPH2] = (uint32_t(*)[128][SPH2])(dyn + 2 * AS_WORDS);

    const int tid = threadIdx.x, lane = tid & 31, wid = tid >> 5;
    const int warpM = wid >> 1, warpN = wid & 1;
    const int g = lane >> 2, t = lane & 3;

    const __half* Abase = h16 + ((size_t)blockIdx.x * 256 + tid) * E_;
    const int wrow = tid & 127;
    const bool wldr = (tid < 128);

    const uint32_t ASO = AS_WORDS * 4, WSO = WS_WORDS * 4;
    uint32_t aA[4], bA[8];
    #pragma unroll
    for (int mf = 0; mf < 4; mf++)
        aA[mf] = (uint32_t)__cvta_generic_to_shared(
            &As[0][warpM * 64 + mf * 16 + (lane & 15)][4 * (lane >> 4)]);
    #pragma unroll
    for (int nf = 0; nf < 8; nf++)
        bA[nf] = (uint32_t)__cvta_generic_to_shared(
            &Ws[0][warpN * 64 + nf * 8 + (lane & 7)][4 * ((lane >> 3) & 1)]);

    float sacc[4][2] = {};

    const int tile0 = blockIdx.y * 5;
    for (int tile = tile0; tile < tile0 + 5; tile++) {
        const int nb = tile * 128;
        const bool wv = wldr && (nb + wrow) < D_;
        const __half* Wbase = w16 + (size_t)(nb + wrow) * E_;

        uint4 ra[4], rw[4];
        float acc[4][8][4] = {};

        auto loadA = [&](int ti) {
            const uint4* p = (const uint4*)(Abase + ti * 32);
            ra[0] = p[0]; ra[1] = p[1]; ra[2] = p[2]; ra[3] = p[3];
        };
        auto loadW = [&](int ti) {
            if (wv) {
                const uint4* p = (const uint4*)(Wbase + ti * 32);
                rw[0] = p[0]; rw[1] = p[1]; rw[2] = p[2]; rw[3] = p[3];
            } else if (wldr) {
                rw[0] = rw[1] = rw[2] = rw[3] = make_uint4(0, 0, 0, 0);
            }
        };
        auto stsAB = [&](int buf) {
            uint4* pa = (uint4*)&As[buf][tid][0];
            pa[0] = ra[0]; pa[1] = ra[1]; pa[2] = ra[2]; pa[3] = ra[3];
            if (wldr) {
                uint4* pw = (uint4*)&Ws[buf][wrow][0];
                pw[0] = rw[0]; pw[1] = rw[1]; pw[2] = rw[2]; pw[3] = rw[3];
            }
        };
        auto domma = [&](int buf) {
            const uint32_t ao = buf * ASO, wo = buf * WSO;
            #pragma unroll
            for (int ks = 0; ks < 2; ks++) {
                uint32_t b[8][2];
                #pragma unroll
                for (int nf = 0; nf < 8; nf++) ldsm2(b[nf], bA[nf] + wo + ks * 32);
                #pragma unroll
                for (int mf = 0; mf < 4; mf++) {
                    uint32_t a[4];
                    ldsm4(a, aA[mf] + ao + ks * 32);
                    #pragma unroll
                    for (int nf = 0; nf < 8; nf++)
                        mma_f16(acc[mf][nf], a, b[nf][0], b[nf][1]);
                }
            }
        };

        loadA(0); loadW(0);
        __syncthreads();
        stsAB(0);
        loadA(1); loadW(1);

        for (int ti = 0; ti < E_ / 32; ti++) {
            __syncthreads();
            if (ti + 1 < E_ / 32) stsAB((ti + 1) & 1);
            if (ti + 2 < E_ / 32) { loadA(ti + 2); loadW(ti + 2); }
            domma(ti & 1);
        }

        // epilogue: + (qp0+qp1+qp2+ba1), relu, * Wa2, accumulate per-row
        #pragma unroll
        for (int mf = 0; mf < 4; mf++) {
            const int r0 = warpM * 64 + mf * 16 + g;
            const int b0 = r0 & 63, b1 = (r0 + 8) & 63;
            #pragma unroll
            for (int nf = 0; nf < 8; nf++) {
                const int col = nb + warpN * 64 + nf * 8 + 2 * t;
                if (col < D_) {
                    float2 w  = *(const float2*)(Wa2 + col);
                    float2 bb = *(const float2*)(ba1 + col);
                    size_t i0 = (size_t)b0 * D_ + col, i1 = (size_t)b1 * D_ + col;
                    float2 a0 = *(const float2*)(qp0 + i0);
                    float2 a1v = *(const float2*)(qp1 + i0);
                    float2 a2 = *(const float2*)(qp2 + i0);
                    float2 c0 = *(const float2*)(qp0 + i1);
                    float2 c1 = *(const float2*)(qp1 + i1);
                    float2 c2 = *(const float2*)(qp2 + i1);
                    float q0x = bb.x + a0.x + a1v.x + a2.x;
                    float q0y = bb.y + a0.y + a1v.y + a2.y;
                    float q1x = bb.x + c0.x + c1.x + c2.x;
                    float q1y = bb.y + c0.y + c1.y + c2.y;
                    sacc[mf][0] += fmaxf(acc[mf][nf][0] + q0x, 0.f) * w.x
                                 + fmaxf(acc[mf][nf][1] + q0y, 0.f) * w.y;
                    sacc[mf][1] += fmaxf(acc[mf][nf][2] + q1x, 0.f) * w.x
                                 + fmaxf(acc[mf][nf][3] + q1y, 0.f) * w.y;
                }
            }
        }
    }

    __syncthreads();
    float* red = (float*)dyn;        // [256][9] overlay
    #pragma unroll
    for (int mf = 0; mf < 4; mf++) {
        const int r0 = warpM * 64 + mf * 16 + g;
        red[r0 * 9 + warpN * 4 + t]       = sacc[mf][0];
        red[(r0 + 8) * 9 + warpN * 4 + t] = sacc[mf][1];
    }
    __syncthreads();
    {
        const int row = tid;
        float a = 0.f;
        #pragma unroll
        for (int c = 0; c < 8; c++) a += red[row * 9 + c];
        const int s = blockIdx.x * 4 + (row >> 6);
        const int b = row & 63;
        spart[(size_t)blockIdx.y * S_ * B_ + (size_t)s * B_ + b] = a;
    }
}

// ---------------------------------------------------------------------------
// Small kernels (unchanged)
// ---------------------------------------------------------------------------
__global__ void havg_kernel(const float* __restrict__ h, float* __restrict__ havg)
{
    int b = blockIdx.x;
    int e = blockIdx.y * 256 + threadIdx.x;
    float s = 0.f;
    for (int si = 0; si < S_; si++)
        s += h[((size_t)si * B_ + b) * E_ + e];
    havg[(size_t)b * E_ + e] = s * (1.f / (float)S_);
}

__global__ __launch_bounds__(256) void softmax_beta_kernel(
    const float* __restrict__ spart,
    const float* __restrict__ hp0, const float* __restrict__ hp1,
    const float* __restrict__ hp2, const float* __restrict__ bh2,
    const float* __restrict__ Wb, const float* __restrict__ bb,
    const float* __restrict__ ba2,
    float* __restrict__ aw_out, float* __restrict__ beta)
{
    int b = blockIdx.x, tid = threadIdx.x;
    __shared__ float sm[256];

    float p = 0.f;
    for (int d = tid; d < D_; d += 256) {
        size_t i = (size_t)b * D_ + d;
        float hv = hp0[i] + hp1[i] + hp2[i] + bh2[d];
        p = fmaf(hv, Wb[d], p);
    }
    sm[tid] = p; __syncthreads();
    for (int o = 128; o > 0; o >>= 1) { if (tid < o) sm[tid] += sm[tid + o]; __syncthreads(); }
    if (tid == 0) beta[b] = 1.f / (1.f + expf(-(sm[0] + bb[0])));
    __syncthreads();

    float v = -3.4e38f;
    if (tid < S_) {
        size_t idx = (size_t)tid * B_ + b;
        v = spart[idx] + spart[(size_t)S_ * B_ + idx] + spart[2 * (size_t)S_ * B_ + idx] + ba2[0];
    }
    sm[tid] = v; __syncthreads();
    for (int o = 128; o > 0; o >>= 1) { if (tid < o) sm[tid] = fmaxf(sm[tid], sm[tid + o]); __syncthreads(); }
    float mx = sm[0]; __syncthreads();
    float e = (tid < S_) ? expf(v - mx) : 0.f;
    sm[tid] = e; __syncthreads();
    for (int o = 128; o > 0; o >>= 1) { if (tid < o) sm[tid] += sm[tid + o]; __syncthreads(); }
    float inv = 1.f / sm[0];
    if (tid < S_) aw_out[(size_t)tid * B_ + b] = e * inv;
}

__global__ void ctx_kernel(const float* __restrict__ h, const float* __restrict__ aw,
                           const float* __restrict__ beta, float* __restrict__ ctx)
{
    int b = blockIdx.x;
    int e = blockIdx.y * 256 + threadIdx.x;
    float s = 0.f;
    for (int si = 0; si < S_; si++)
        s = fmaf(aw[(size_t)si * B_ + b], h[((size_t)si * B_ + b) * E_ + e], s);
    ctx[(size_t)b * E_ + e] = s * beta[b];
}

__global__ __launch_bounds__(256) void argmax_kernel(const float* __restrict__ y, int* __restrict__ amax)
{
    int b = blockIdx.x, tid = threadIdx.x;
    float bm = -3.4e38f; int bi = 0;
    for (int i = tid; i < V_; i += 256) {
        float v = y[(size_t)b * V_ + i];
        if (v > bm) { bm = v; bi = i; }
    }
    __shared__ float sv[256];
    __shared__ int si_[256];
    sv[tid] = bm; si_[tid] = bi; __syncthreads();
    for (int o = 128; o > 0; o >>= 1) {
        if (tid < o) {
            if (sv[tid + o] > sv[tid] || (sv[tid + o] == sv[tid] && si_[tid + o] < si_[tid])) {
                sv[tid] = sv[tid + o]; si_[tid] = si_[tid + o];
            }
        }
        __syncthreads();
    }
    if (tid == 0) amax[b] = si_[0];
}

__global__ void xbuild_kernel(const float* __restrict__ emb, const int* __restrict__ Etm1,
                              const float* __restrict__ ctx, float* __restrict__ x)
{
    int b = blockIdx.x;
    int i = blockIdx.y * 256 + threadIdx.x;
    if (i < W_) x[(size_t)b * WE_ + i] = emb[(size_t)Etm1[b] * W_ + i];
    else        x[(size_t)b * WE_ + i] = ctx[(size_t)b * E_ + (i - W_)];
}

__global__ void lstm_kernel(const float* __restrict__ gp0, const float* __restrict__ gp1,
                            const float* __restrict__ b_ih, const float* __restrict__ b_hh,
                            const float* __restrict__ cp0, const float* __restrict__ cp1,
                            const float* __restrict__ cp2, const float* __restrict__ bc2,
                            float* __restrict__ out, float* __restrict__ z)
{
    int b = blockIdx.x;
    int d = blockIdx.y * 256 + threadIdx.x;
    if (d >= D_) return;
    const size_t base = (size_t)b * 4 * D_;
    float gi = gp0[base + d]          + gp1[base + d]          + b_ih[d]          + b_hh[d];
    float gf = gp0[base + D_ + d]     + gp1[base + D_ + d]     + b_ih[D_ + d]     + b_hh[D_ + d];
    float gg = gp0[base + 2*D_ + d]   + gp1[base + 2*D_ + d]   + b_ih[2*D_ + d]   + b_hh[2*D_ + d];
    float go = gp0[base + 3*D_ + d]   + gp1[base + 3*D_ + d]   + b_ih[3*D_ + d]   + b_hh[3*D_ + d];
    size_t ci = (size_t)b * D_ + d;
    float c0 = cp0[ci] + cp1[ci] + cp2[ci] + bc2[d];
    float ig = 1.f / (1.f + expf(-gi));
    float fg = 1.f / (1.f + expf(-gf));
    float gt = tanhf(gg);
    float og = 1.f / (1.f + expf(-go));
    float c = fmaf(fg, c0, ig * gt);
    float ht = og * tanhf(c);
    out[(size_t)B_ * V_ + (size_t)b * D_ + d] = ht;
    out[(size_t)B_ * V_ + (size_t)B_ * D_ + (size_t)b * D_ + d] = c;
    z[(size_t)b * DWE_ + d] = ht;
}

__global__ void zbuild_kernel(const float* __restrict__ emb, const int* __restrict__ amax,
                              const float* __restrict__ ctx, float* __restrict__ z)
{
    int b = blockIdx.x;
    int i = blockIdx.y * 256 + threadIdx.x;
    if (i < W_) z[(size_t)b * DWE_ + D_ + i] = emb[(size_t)amax[b] * W_ + i];
    else        z[(size_t)b * DWE_ + D_ + i] = ctx[(size_t)b * E_ + (i - W_)];
}

// ---------------------------------------------------------------------------
// Launch
// ---------------------------------------------------------------------------
extern "C" void kernel_launch(void* const* d_in, const int* in_sizes, int n_in,
                              void* d_out, int out_size)
{
    const int*   E_tm1 = (const int*)d_in[0];
    const float* y_tm1 = (const float*)d_in[1];
    const float* h     = (const float*)d_in[2];
    const float* emb   = (const float*)d_in[3];
    const float* W_ih  = (const float*)d_in[4];
    const float* b_ih  = (const float*)d_in[5];
    const float* W_hh  = (const float*)d_in[6];
    const float* b_hh  = (const float*)d_in[7];
    const float* W_out = (const float*)d_in[8];
    const float* b_out = (const float*)d_in[9];
    const float* Wh1 = (const float*)d_in[10]; const float* bh1 = (const float*)d_in[11];
    const float* Wh2 = (const float*)d_in[12]; const float* bh2 = (const float*)d_in[13];
    const float* Wc1 = (const float*)d_in[14]; const float* bc1 = (const float*)d_in[15];
    const float* Wc2 = (const float*)d_in[16]; const float* bc2 = (const float*)d_in[17];
    const float* Wa1 = (const float*)d_in[18]; const float* ba1 = (const float*)d_in[19];
    const float* Wa2 = (const float*)d_in[20]; const float* ba2 = (const float*)d_in[21];
    const float* Wb  = (const float*)d_in[22]; const float* bb  = (const float*)d_in[23];
    float* out = (float*)d_out;

    Scratch* s = nullptr;
    cudaGetSymbolAddress((void**)&s, g_s);

    cudaFuncSetAttribute(mma_scores_kernel,
                         cudaFuncAttributeMaxDynamicSharedMemorySize, SC_DYN);

    const int GN_D  = (D_ + 63) / 64;            // 29
    const int GN_4D = (4 * D_ + 127) / 128;      // 57
    const int GN_V  = V_ / 128;                  // 250
    const int CONV_BLK = (S_ * B_ * E_ / 8 + D_ * E_ / 8 + 255) / 256;  // 7172

    // 0. fp16 preconversion of h and Wa1 key-slice
    conv16_kernel<<<CONV_BLK, 256>>>(h, Wa1, s->h16, s->w16);

    // 1. encoder mean
    havg_kernel<<<dim3(B_, E_ / 256), 256>>>(h, s->havg);

    // 2. init-state layer1 -> partials (KS=2)
    {
        SKJob2 jj;
        jj.j[0] = {s->havg, nullptr, nullptr, nullptr, 0, Wh1, E_, E_, D_, s->skpA[0][0]};
        jj.j[1] = {s->havg, nullptr, nullptr, nullptr, 0, Wc1, E_, E_, D_, s->skpA[1][0]};
        sk_gemm_kernel<64><<<dim3(GN_D, 2, 2), 256>>>(jj);
    }
    // 3. layer2, A = relu(sum L1 partials + b1) fused (KS=3)
    {
        SKJob2 jj;
        jj.j[0] = {s->skpA[0][0], s->skpA[0][1], nullptr, bh1, 1, Wh2, D_, D_, D_, s->skpB[0][0]};
        jj.j[1] = {s->skpA[1][0], s->skpA[1][1], nullptr, bc1, 1, Wc2, D_, D_, D_, s->skpB[1][0]};
        sk_gemm_kernel<64><<<dim3(GN_D, 2, 3), 256>>>(jj);
    }
    // 4. qpart partials = (h0 = sum L2 partials + bh2) @ Wa1[:, :D]^T  (KS=3)
    {
        SKJob2 jj;
        jj.j[0] = {s->skpB[0][0], s->skpB[0][1], s->skpB[0][2], bh2, 0, Wa1, D_, DE_, D_, s->skpA[0][0]};
        jj.j[1] = jj.j[0];
        sk_gemm_kernel<64><<<dim3(GN_D, 1, 3), 256>>>(jj);
    }

    // 5. fused scores GEMM (fp16, preconverted; qpart reduce fused in epilogue)
    mma_scores_kernel<<<dim3(S_ / 4, 3), 256, SC_DYN>>>(
        s->h16, s->w16,
        s->skpA[0][0], s->skpA[0][0] + (size_t)B_ * D_, s->skpA[0][0] + 2 * (size_t)B_ * D_,
        ba1, Wa2, s->spart);

    // 6. argmax of y_tm1
    argmax_kernel<<<B_, 256>>>(y_tm1, s->amax);

    // 7. softmax + beta (h0 virtual from partials)
    float* aw_out = out + (size_t)B_ * V_ + 2 * (size_t)B_ * D_;
    softmax_beta_kernel<<<B_, 256>>>(s->spart, s->skpB[0][0], s->skpB[0][1], s->skpB[0][2],
                                     bh2, Wb, bb, ba2, aw_out, s->beta);

    // 8. context
    ctx_kernel<<<dim3(B_, E_ / 256), 256>>>(h, aw_out, s->beta, s->ctx);

    // 9. LSTM input + gates (h0 virtual in job1)
    xbuild_kernel<<<dim3(B_, WE_ / 256), 256>>>(emb, E_tm1, s->ctx, s->x);
    {
        SKJob2 jj;
        jj.j[0] = {s->x, nullptr, nullptr, nullptr, 0, W_ih, WE_, WE_, 4 * D_, s->gp0};
        jj.j[1] = {s->skpB[0][0], s->skpB[0][1], s->skpB[0][2], bh2, 0, W_hh, D_, D_, 4 * D_, s->gp1};
        sk_gemm_kernel<128><<<dim3(GN_4D, 2, 1), 256>>>(jj);
    }

    // 10. LSTM pointwise (c0 virtual from partials)
    lstm_kernel<<<dim3(B_, (D_ + 255) / 256), 256>>>(
        s->gp0, s->gp1, b_ih, b_hh,
        s->skpB[1][0], s->skpB[1][1], s->skpB[1][2], bc2, out, s->z);

    // 11. z tail
    zbuild_kernel<<<dim3(B_, WE_ / 256), 256>>>(emb, s->amax, s->ctx, s->z);

    // 12. logits
    logits_kernel<<<GN_V, 256>>>(s->z, W_out, b_out, out);
}

// round 11
// speedup vs baseline: 1.0744x; 1.0705x over previous
#include <cuda_runtime.h>
#include <cuda_fp16.h>
#include <math.h>
#include <stdint.h>

#define S_ 196
#define B_ 64
#define E_ 1024
#define D_ 1800
#define W_ 512
#define V_ 32000
#define WE_ (W_ + E_)       // 1536
#define DE_ (D_ + E_)       // 2824
#define DWE_ (D_ + W_ + E_) // 3336

// ---------------------------------------------------------------------------
// Scratch
// ---------------------------------------------------------------------------
struct Scratch {
    float havg[B_ * E_];
    float skpA[2][3][B_ * D_];
    float skpB[2][3][B_ * D_];
    float qpart[B_ * D_];
    float spart[3 * S_ * B_];
    float beta[B_];
    float ctx[B_ * E_];
    float x[B_ * WE_];
    float z[B_ * DWE_];
    float gp0[B_ * 4 * D_];
    float gp1[B_ * 4 * D_];
    int   amax[B_];
    __half h16[S_ * B_ * E_];   // fp16 copy of h
    __half w16[D_ * E_];        // fp16 copy of Wa1[:, D:]
};
__device__ Scratch g_s;

// ---------------------------------------------------------------------------
// fp16 MMA helpers
// ---------------------------------------------------------------------------
__device__ __forceinline__ uint32_t packh2(float a, float b) {
    __half2 h = __floats2half2_rn(a, b);
    return *(uint32_t*)&h;
}
__device__ __forceinline__ void mma_f16(float (&c)[4], const uint32_t (&a)[4],
                                        const uint32_t b0, const uint32_t b1) {
    asm volatile(
        "mma.sync.aligned.m16n8k16.row.col.f32.f16.f16.f32 "
        "{%0,%1,%2,%3},{%4,%5,%6,%7},{%8,%9},{%0,%1,%2,%3};"
        : "+f"(c[0]), "+f"(c[1]), "+f"(c[2]), "+f"(c[3])
        : "r"(a[0]), "r"(a[1]), "r"(a[2]), "r"(a[3]), "r"(b0), "r"(b1));
}
__device__ __forceinline__ void ldsm4(uint32_t (&r)[4], uint32_t addr) {
    asm volatile("ldmatrix.sync.aligned.m8n8.x4.shared.b16 {%0,%1,%2,%3}, [%4];"
        : "=r"(r[0]), "=r"(r[1]), "=r"(r[2]), "=r"(r[3]) : "r"(addr));
}
__device__ __forceinline__ void ldsm2(uint32_t (&r)[2], uint32_t addr) {
    asm volatile("ldmatrix.sync.aligned.m8n8.x2.shared.b16 {%0,%1}, [%2];"
        : "=r"(r[0]), "=r"(r[1]) : "r"(addr));
}
__device__ __forceinline__ void ld8(float* d, const float* p) {
    float4 a = ((const float4*)p)[0], b = ((const float4*)p)[1];
    d[0]=a.x; d[1]=a.y; d[2]=a.z; d[3]=a.w; d[4]=b.x; d[5]=b.y; d[6]=b.z; d[7]=b.w;
}
__device__ __forceinline__ void add8(float* d, const float* p) {
    float4 a = ((const float4*)p)[0], b = ((const float4*)p)[1];
    d[0]+=a.x; d[1]+=a.y; d[2]+=a.z; d[3]+=a.w; d[4]+=b.x; d[5]+=b.y; d[6]+=b.z; d[7]+=b.w;
}

// Row stride 20 uint32: 8-row base pattern {0,20,8,28,16,4,24,12} mod 32 ->
// conflict-free LDSM row fetches and STS.128 phases.
#define SPADH 20

// ---------------------------------------------------------------------------
// fp32 -> fp16 preconversion: h16 = h, w16 = Wa1[:, D:] (row stride E)
// ---------------------------------------------------------------------------
__global__ __launch_bounds__(256) void conv16_kernel(
    const float* __restrict__ h, const float* __restrict__ Wa1,
    __half* __restrict__ h16, __half* __restrict__ w16)
{
    const int HT = S_ * B_ * E_ / 8;       // octets in h
    const int WT = D_ * E_ / 8;            // octets in w16
    int idx = blockIdx.x * 256 + threadIdx.x;
    if (idx < HT) {
        const float4* p = (const float4*)(h + (size_t)idx * 8);
        float4 a = p[0], b = p[1];
        *(uint4*)(h16 + (size_t)idx * 8) =
            make_uint4(packh2(a.x, a.y), packh2(a.z, a.w),
                       packh2(b.x, b.y), packh2(b.z, b.w));
    } else if (idx - HT < WT) {
        int j = idx - HT;
        int n = j / (E_ / 8), k8 = j % (E_ / 8);
        const float4* p = (const float4*)(Wa1 + (size_t)n * DE_ + D_ + k8 * 8);
        float4 a = p[0], b = p[1];
        *(uint4*)(w16 + (size_t)n * E_ + k8 * 8) =
            make_uint4(packh2(a.x, a.y), packh2(a.z, a.w),
                       packh2(b.x, b.y), packh2(b.z, b.w));
    }
}

// ---------------------------------------------------------------------------
// Small-GEMM K-segment, fp16 MMA, fused A-side reduce
// ---------------------------------------------------------------------------
struct SKJob {
    const float* A0; const float* A1p; const float* A2p;
    const float* kb; int krelu;
    const float* W; int K; int ldw; int N; float* Cpart;
};
struct SKJob2 { SKJob j[2]; };

template<int BN>
__device__ __forceinline__ void seg64(
    const SKJob& j, const int nb, const int t0, const int t1,
    uint32_t As[64][SPADH], uint32_t Ws[BN][SPADH],
    float (&acc)[2][BN / 32][4])
{
    constexpr int NF  = BN / 32;
    constexpr int WPT = (BN == 64) ? 8 : 16;
    const int tid  = threadIdx.x;
    const int lane = tid & 31, wid = tid >> 5;
    const int warpM = wid >> 2, warpN = wid & 3;

    const int am  = tid & 63, akg = (tid >> 6) * 8;
    const int wn  = (BN == 64) ? (tid & 63) : (tid & 127);
    const int wkg = (BN == 64) ? ((tid >> 6) * 8) : ((tid >> 7) * 16);
    const bool wvalid = (nb + wn) < j.N;
    const int K = j.K;
    const float* A0r = j.A0 + (size_t)am * K;
    const float* A1r = j.A1p ? j.A1p + (size_t)am * K : nullptr;
    const float* A2r = j.A2p ? j.A2p + (size_t)am * K : nullptr;
    const float* Wbase = j.W + (size_t)(nb + wn) * j.ldw;

    uint32_t aAddr[2][2], bAddr[NF];
    #pragma unroll
    for (int mf = 0; mf < 2; mf++)
        #pragma unroll
        for (int ks = 0; ks < 2; ks++)
            aAddr[mf][ks] = (uint32_t)__cvta_generic_to_shared(
                &As[warpM * 32 + mf * 16 + (lane & 15)][ks * 8 + 4 * (lane >> 4)]);
    #pragma unroll
    for (int nf = 0; nf < NF; nf++)
        bAddr[nf] = (uint32_t)__cvta_generic_to_shared(
            &Ws[warpN * (BN / 4) + nf * 8 + (lane & 7)][4 * (lane >> 3)]);

    float ra[8], rw[WPT];

    auto loadA = [&](int ti) {
        const int k0 = ti * 32 + akg;
        if (k0 + 8 <= K) {
            ld8(ra, A0r + k0);
            if (A1r) add8(ra, A1r + k0);
            if (A2r) add8(ra, A2r + k0);
            if (j.kb) add8(ra, j.kb + k0);
        } else {
            #pragma unroll
            for (int i = 0; i < 8; i++) {
                int k = k0 + i; float v = 0.f;
                if (k < K) {
                    v = A0r[k];
                    if (A1r) v += A1r[k];
                    if (A2r) v += A2r[k];
                    if (j.kb) v += j.kb[k];
                }
                ra[i] = v;
            }
        }
        if (j.krelu) {
            #pragma unroll
            for (int i = 0; i < 8; i++) ra[i] = fmaxf(ra[i], 0.f);
        }
    };
    auto loadW = [&](int ti) {
        const int k0 = ti * 32 + wkg;
        if (wvalid && k0 + WPT <= K) {
            #pragma unroll
            for (int i = 0; i < WPT / 4; i++) {
                float4 v = *(const float4*)(Wbase + k0 + i * 4);
                rw[i*4+0]=v.x; rw[i*4+1]=v.y; rw[i*4+2]=v.z; rw[i*4+3]=v.w;
            }
        } else {
            #pragma unroll
            for (int i = 0; i < WPT; i++)
                rw[i] = (wvalid && (k0 + i) < K) ? Wbase[k0 + i] : 0.f;
        }
    };

    loadA(t0);
    loadW(t0);

    for (int ti = t0; ti < t1; ti++) {
        __syncthreads();
        *(uint4*)&As[am][akg >> 1] =
            make_uint4(packh2(ra[0], ra[1]), packh2(ra[2], ra[3]),
                       packh2(ra[4], ra[5]), packh2(ra[6], ra[7]));
        #pragma unroll
        for (int h8 = 0; h8 < WPT / 8; h8++) {
            const float* r = rw + h8 * 8;
            *(uint4*)&Ws[wn][(wkg >> 1) + h8 * 4] =
                make_uint4(packh2(r[0], r[1]), packh2(r[2], r[3]),
                           packh2(r[4], r[5]), packh2(r[6], r[7]));
        }
        __syncthreads();

        if (ti + 1 < t1) { loadA(ti + 1); loadW(ti + 1); }

        uint32_t b[NF][4];
        #pragma unroll
        for (int nf = 0; nf < NF; nf++) ldsm4(b[nf], bAddr[nf]);
        #pragma unroll
        for (int ks = 0; ks < 2; ks++) {
            uint32_t a[2][4];
            ldsm4(a[0], aAddr[0][ks]);
            ldsm4(a[1], aAddr[1][ks]);
            #pragma unroll
            for (int nf = 0; nf < NF; nf++) {
                mma_f16(acc[0][nf], a[0], b[nf][2 * ks], b[nf][2 * ks + 1]);
                mma_f16(acc[1][nf], a[1], b[nf][2 * ks], b[nf][2 * ks + 1]);
            }
        }
    }
}

template<int BN>
__global__ __launch_bounds__(256) void sk_gemm_kernel(SKJob2 jobs)
{
    constexpr int NF = BN / 32;
    __shared__ __align__(16) uint32_t As[64][SPADH];
    __shared__ __align__(16) uint32_t Ws[BN][SPADH];

    const SKJob j = jobs.j[blockIdx.y];
    const int nb = blockIdx.x * BN;
    if (nb >= j.N) return;

    const int tiles = (j.K + 31) >> 5;
    const int KS = gridDim.z, kz = blockIdx.z;
    const int tpk = (tiles + KS - 1) / KS;
    const int t0 = kz * tpk;
    const int t1 = (t0 + tpk < tiles) ? (t0 + tpk) : tiles;

    float acc[2][NF][4] = {};
    if (t0 < t1)
        seg64<BN>(j, nb, t0, t1, As, Ws, acc);

    float* C = j.Cpart + (size_t)kz * 64 * j.N;
    const int tid = threadIdx.x, lane = tid & 31, wid = tid >> 5;
    const int warpM = wid >> 2, warpN = wid & 3;
    const int g = lane >> 2, t = lane & 3;

    #pragma unroll
    for (int mf = 0; mf < 2; mf++) {
        const int row = warpM * 32 + mf * 16 + g;
        #pragma unroll
        for (int nf = 0; nf < NF; nf++) {
            const int col = nb + warpN * (BN / 4) + nf * 8 + 2 * t;
            if (col < j.N) {
                *(float2*)&C[(size_t)row * j.N + col]       = make_float2(acc[mf][nf][0], acc[mf][nf][1]);
                *(float2*)&C[(size_t)(row + 8) * j.N + col] = make_float2(acc[mf][nf][2], acc[mf][nf][3]);
            }
        }
    }
}

// qpart reduce: 3 partials + bias
__global__ __launch_bounds__(256) void sk_reduce3_kernel(
    const float* __restrict__ part, const float* __restrict__ bias,
    float* __restrict__ outp)
{
    int idx = blockIdx.x * 256 + threadIdx.x;
    if (idx >= B_ * D_) return;
    int n = idx % D_;
    float v = bias[n] + part[idx] + part[(size_t)B_ * D_ + idx] + part[2 * (size_t)B_ * D_ + idx];
    outp[idx] = v;
}

__global__ __launch_bounds__(256) void logits_kernel(
    const float* __restrict__ z, const float* __restrict__ Wt,
    const float* __restrict__ bias, float* __restrict__ C)
{
    __shared__ __align__(16) uint32_t As[64][SPADH];
    __shared__ __align__(16) uint32_t Ws[128][SPADH];

    SKJob j; j.A0 = z; j.A1p = nullptr; j.A2p = nullptr; j.kb = nullptr; j.krelu = 0;
    j.W = Wt; j.K = DWE_; j.ldw = DWE_; j.N = V_; j.Cpart = nullptr;
    const int nb = blockIdx.x * 128;

    float acc[2][4][4] = {};
    seg64<128>(j, nb, 0, (DWE_ + 31) >> 5, As, Ws, acc);

    const int tid = threadIdx.x, lane = tid & 31, wid = tid >> 5;
    const int warpM = wid >> 2, warpN = wid & 3;
    const int g = lane >> 2, t = lane & 3;

    #pragma unroll
    for (int mf = 0; mf < 2; mf++) {
        const int row = warpM * 32 + mf * 16 + g;
        #pragma unroll
        for (int nf = 0; nf < 4; nf++) {
            const int col = nb + warpN * 32 + nf * 8 + 2 * t;
            float b0 = bias[col], b1 = bias[col + 1];
            *(float2*)&C[(size_t)row * V_ + col]       = make_float2(acc[mf][nf][0] + b0, acc[mf][nf][1] + b1);
            *(float2*)&C[(size_t)(row + 8) * V_ + col] = make_float2(acc[mf][nf][2] + b0, acc[mf][nf][3] + b1);
        }
    }
}

// ---------------------------------------------------------------------------
// Fused attention scores: preconverted fp16 inputs, ktile=32, ping-pong
// dynamic smem (1 sync/iter), materialized qpart in epilogue.
// BM=256 (4 seq), BN=128, 8 warps (4M x 2N), warp tile 64x64. grid = (49, 3).
// ---------------------------------------------------------------------------
#define SPH2 20
#define AS_WORDS (256 * SPH2)
#define WS_WORDS (128 * SPH2)
#define SC_DYN ((2 * AS_WORDS + 2 * WS_WORDS) * 4)   // 61440 B

__global__ __launch_bounds__(256, 1) void mma_scores_kernel(
    const __half* __restrict__ h16, const __half* __restrict__ w16,
    const float* __restrict__ qpart, const float* __restrict__ Wa2,
    float* __restrict__ spart)
{
    extern __shared__ uint32_t dyn[];
    uint32_t (*As)[256][SPH2] = (uint32_t(*)[256][SPH2])dyn;
    uint32_t (*Ws)[128][SPH2] = (uint32_t(*)[128][SPH2])(dyn + 2 * AS_WORDS);

    const int tid = threadIdx.x, lane = tid & 31, wid = tid >> 5;
    const int warpM = wid >> 1, warpN = wid & 1;
    const int g = lane >> 2, t = lane & 3;

    const __half* Abase = h16 + ((size_t)blockIdx.x * 256 + tid) * E_;
    const int wrow = tid & 127;
    const bool wldr = (tid < 128);

    const uint32_t ASO = AS_WORDS * 4, WSO = WS_WORDS * 4;
    uint32_t aA[4], bA[8];
    #pragma unroll
    for (int mf = 0; mf < 4; mf++)
        aA[mf] = (uint32_t)__cvta_generic_to_shared(
            &As[0][warpM * 64 + mf * 16 + (lane & 15)][4 * (lane >> 4)]);
    #pragma unroll
    for (int nf = 0; nf < 8; nf++)
        bA[nf] = (uint32_t)__cvta_generic_to_shared(
            &Ws[0][warpN * 64 + nf * 8 + (lane & 7)][4 * ((lane >> 3) & 1)]);

    float sacc[4][2] = {};

    const int tile0 = blockIdx.y * 5;
    for (int tile = tile0; tile < tile0 + 5; tile++) {
        const int nb = tile * 128;
        const bool wv = wldr && (nb + wrow) < D_;
        const __half* Wbase = w16 + (size_t)(nb + wrow) * E_;

        uint4 ra[4], rw[4];
        float acc[4][8][4] = {};

        auto loadA = [&](int ti) {
            const uint4* p = (const uint4*)(Abase + ti * 32);
            ra[0] = p[0]; ra[1] = p[1]; ra[2] = p[2]; ra[3] = p[3];
        };
        auto loadW = [&](int ti) {
            if (wv) {
                const uint4* p = (const uint4*)(Wbase + ti * 32);
                rw[0] = p[0]; rw[1] = p[1]; rw[2] = p[2]; rw[3] = p[3];
            } else if (wldr) {
                rw[0] = rw[1] = rw[2] = rw[3] = make_uint4(0, 0, 0, 0);
            }
        };
        auto stsAB = [&](int buf) {
            uint4* pa = (uint4*)&As[buf][tid][0];
            pa[0] = ra[0]; pa[1] = ra[1]; pa[2] = ra[2]; pa[3] = ra[3];
            if (wldr) {
                uint4* pw = (uint4*)&Ws[buf][wrow][0];
                pw[0] = rw[0]; pw[1] = rw[1]; pw[2] = rw[2]; pw[3] = rw[3];
            }
        };
        auto domma = [&](int buf) {
            const uint32_t ao = buf * ASO, wo = buf * WSO;
            #pragma unroll
            for (int ks = 0; ks < 2; ks++) {
                uint32_t b[8][2];
                #pragma unroll
                for (int nf = 0; nf < 8; nf++) ldsm2(b[nf], bA[nf] + wo + ks * 32);
                #pragma unroll
                for (int mf = 0; mf < 4; mf++) {
                    uint32_t a[4];
                    ldsm4(a, aA[mf] + ao + ks * 32);
                    #pragma unroll
                    for (int nf = 0; nf < 8; nf++)
                        mma_f16(acc[mf][nf], a, b[nf][0], b[nf][1]);
                }
            }
        };

        loadA(0); loadW(0);
        __syncthreads();
        stsAB(0);
        loadA(1); loadW(1);

        for (int ti = 0; ti < E_ / 32; ti++) {
            __syncthreads();
            if (ti + 1 < E_ / 32) stsAB((ti + 1) & 1);
            if (ti + 2 < E_ / 32) { loadA(ti + 2); loadW(ti + 2); }
            domma(ti & 1);
        }

        // epilogue: + qpart, relu, * Wa2, accumulate per-row
        #pragma unroll
        for (int mf = 0; mf < 4; mf++) {
            const int r0 = warpM * 64 + mf * 16 + g;
            const int b0 = r0 & 63, b1 = (r0 + 8) & 63;
            #pragma unroll
            for (int nf = 0; nf < 8; nf++) {
                const int col = nb + warpN * 64 + nf * 8 + 2 * t;
                if (col < D_) {
                    float2 w  = *(const float2*)(Wa2 + col);
                    float2 q0 = *(const float2*)(qpart + (size_t)b0 * D_ + col);
                    float2 q1 = *(const float2*)(qpart + (size_t)b1 * D_ + col);
                    sacc[mf][0] += fmaxf(acc[mf][nf][0] + q0.x, 0.f) * w.x
                                 + fmaxf(acc[mf][nf][1] + q0.y, 0.f) * w.y;
                    sacc[mf][1] += fmaxf(acc[mf][nf][2] + q1.x, 0.f) * w.x
                                 + fmaxf(acc[mf][nf][3] + q1.y, 0.f) * w.y;
                }
            }
        }
    }

    __syncthreads();
    float* red = (float*)dyn;        // [256][9] overlay
    #pragma unroll
    for (int mf = 0; mf < 4; mf++) {
        const int r0 = warpM * 64 + mf * 16 + g;
        red[r0 * 9 + warpN * 4 + t]       = sacc[mf][0];
        red[(r0 + 8) * 9 + warpN * 4 + t] = sacc[mf][1];
    }
    __syncthreads();
    {
        const int row = tid;
        float a = 0.f;
        #pragma unroll
        for (int c = 0; c < 8; c++) a += red[row * 9 + c];
        const int s = blockIdx.x * 4 + (row >> 6);
        const int b = row & 63;
        spart[(size_t)blockIdx.y * S_ * B_ + (size_t)s * B_ + b] = a;
    }
}

// ---------------------------------------------------------------------------
// Small kernels (unchanged)
// ---------------------------------------------------------------------------
__global__ void havg_kernel(const float* __restrict__ h, float* __restrict__ havg)
{
    int b = blockIdx.x;
    int e = blockIdx.y * 256 + threadIdx.x;
    float s = 0.f;
    for (int si = 0; si < S_; si++)
        s += h[((size_t)si * B_ + b) * E_ + e];
    havg[(size_t)b * E_ + e] = s * (1.f / (float)S_);
}

__global__ __launch_bounds__(256) void softmax_beta_kernel(
    const float* __restrict__ spart,
    const float* __restrict__ hp0, const float* __restrict__ hp1,
    const float* __restrict__ hp2, const float* __restrict__ bh2,
    const float* __restrict__ Wb, const float* __restrict__ bb,
    const float* __restrict__ ba2,
    float* __restrict__ aw_out, float* __restrict__ beta)
{
    int b = blockIdx.x, tid = threadIdx.x;
    __shared__ float sm[256];

    float p = 0.f;
    for (int d = tid; d < D_; d += 256) {
        size_t i = (size_t)b * D_ + d;
        float hv = hp0[i] + hp1[i] + hp2[i] + bh2[d];
        p = fmaf(hv, Wb[d], p);
    }
    sm[tid] = p; __syncthreads();
    for (int o = 128; o > 0; o >>= 1) { if (tid < o) sm[tid] += sm[tid + o]; __syncthreads(); }
    if (tid == 0) beta[b] = 1.f / (1.f + expf(-(sm[0] + bb[0])));
    __syncthreads();

    float v = -3.4e38f;
    if (tid < S_) {
        size_t idx = (size_t)tid * B_ + b;
        v = spart[idx] + spart[(size_t)S_ * B_ + idx] + spart[2 * (size_t)S_ * B_ + idx] + ba2[0];
    }
    sm[tid] = v; __syncthreads();
    for (int o = 128; o > 0; o >>= 1) { if (tid < o) sm[tid] = fmaxf(sm[tid], sm[tid + o]); __syncthreads(); }
    float mx = sm[0]; __syncthreads();
    float e = (tid < S_) ? expf(v - mx) : 0.f;
    sm[tid] = e; __syncthreads();
    for (int o = 128; o > 0; o >>= 1) { if (tid < o) sm[tid] += sm[tid + o]; __syncthreads(); }
    float inv = 1.f / sm[0];
    if (tid < S_) aw_out[(size_t)tid * B_ + b] = e * inv;
}

__global__ void ctx_kernel(const float* __restrict__ h, const float* __restrict__ aw,
                           const float* __restrict__ beta, float* __restrict__ ctx)
{
    int b = blockIdx.x;
    int e = blockIdx.y * 256 + threadIdx.x;
    float s = 0.f;
    for (int si = 0; si < S_; si++)
        s = fmaf(aw[(size_t)si * B_ + b], h[((size_t)si * B_ + b) * E_ + e], s);
    ctx[(size_t)b * E_ + e] = s * beta[b];
}

__global__ __launch_bounds__(256) void argmax_kernel(const float* __restrict__ y, int* __restrict__ amax)
{
    int b = blockIdx.x, tid = threadIdx.x;
    float bm = -3.4e38f; int bi = 0;
    for (int i = tid; i < V_; i += 256) {
        float v = y[(size_t)b * V_ + i];
        if (v > bm) { bm = v; bi = i; }
    }
    __shared__ float sv[256];
    __shared__ int si_[256];
    sv[tid] = bm; si_[tid] = bi; __syncthreads();
    for (int o = 128; o > 0; o >>= 1) {
        if (tid < o) {
            if (sv[tid + o] > sv[tid] || (sv[tid + o] == sv[tid] && si_[tid + o] < si_[tid])) {
                sv[tid] = sv[tid + o]; si_[tid] = si_[tid + o];
            }
        }
        __syncthreads();
    }
    if (tid == 0) amax[b] = si_[0];
}

__global__ void xbuild_kernel(const float* __restrict__ emb, const int* __restrict__ Etm1,
                              const float* __restrict__ ctx, float* __restrict__ x)
{
    int b = blockIdx.x;
    int i = blockIdx.y * 256 + threadIdx.x;
    if (i < W_) x[(size_t)b * WE_ + i] = emb[(size_t)Etm1[b] * W_ + i];
    else        x[(size_t)b * WE_ + i] = ctx[(size_t)b * E_ + (i - W_)];
}

__global__ void lstm_kernel(const float* __restrict__ gp0, const float* __restrict__ gp1,
                            const float* __restrict__ b_ih, const float* __restrict__ b_hh,
                            const float* __restrict__ cp0, const float* __restrict__ cp1,
                            const float* __restrict__ cp2, const float* __restrict__ bc2,
                            float* __restrict__ out, float* __restrict__ z)
{
    int b = blockIdx.x;
    int d = blockIdx.y * 256 + threadIdx.x;
    if (d >= D_) return;
    const size_t base = (size_t)b * 4 * D_;
    float gi = gp0[base + d]          + gp1[base + d]          + b_ih[d]          + b_hh[d];
    float gf = gp0[base + D_ + d]     + gp1[base + D_ + d]     + b_ih[D_ + d]     + b_hh[D_ + d];
    float gg = gp0[base + 2*D_ + d]   + gp1[base + 2*D_ + d]   + b_ih[2*D_ + d]   + b_hh[2*D_ + d];
    float go = gp0[base + 3*D_ + d]   + gp1[base + 3*D_ + d]   + b_ih[3*D_ + d]   + b_hh[3*D_ + d];
    size_t ci = (size_t)b * D_ + d;
    float c0 = cp0[ci] + cp1[ci] + cp2[ci] + bc2[d];
    float ig = 1.f / (1.f + expf(-gi));
    float fg = 1.f / (1.f + expf(-gf));
    float gt = tanhf(gg);
    float og = 1.f / (1.f + expf(-go));
    float c = fmaf(fg, c0, ig * gt);
    float ht = og * tanhf(c);
    out[(size_t)B_ * V_ + (size_t)b * D_ + d] = ht;
    out[(size_t)B_ * V_ + (size_t)B_ * D_ + (size_t)b * D_ + d] = c;
    z[(size_t)b * DWE_ + d] = ht;
}

__global__ void zbuild_kernel(const float* __restrict__ emb, const int* __restrict__ amax,
                              const float* __restrict__ ctx, float* __restrict__ z)
{
    int b = blockIdx.x;
    int i = blockIdx.y * 256 + threadIdx.x;
    if (i < W_) z[(size_t)b * DWE_ + D_ + i] = emb[(size_t)amax[b] * W_ + i];
    else        z[(size_t)b * DWE_ + D_ + i] = ctx[(size_t)b * E_ + (i - W_)];
}

// ---------------------------------------------------------------------------
// Launch
// ---------------------------------------------------------------------------
extern "C" void kernel_launch(void* const* d_in, const int* in_sizes, int n_in,
                              void* d_out, int out_size)
{
    const int*   E_tm1 = (const int*)d_in[0];
    const float* y_tm1 = (const float*)d_in[1];
    const float* h     = (const float*)d_in[2];
    const float* emb   = (const float*)d_in[3];
    const float* W_ih  = (const float*)d_in[4];
    const float* b_ih  = (const float*)d_in[5];
    const float* W_hh  = (const float*)d_in[6];
    const float* b_hh  = (const float*)d_in[7];
    const float* W_out = (const float*)d_in[8];
    const float* b_out = (const float*)d_in[9];
    const float* Wh1 = (const float*)d_in[10]; const float* bh1 = (const float*)d_in[11];
    const float* Wh2 = (const float*)d_in[12]; const float* bh2 = (const float*)d_in[13];
    const float* Wc1 = (const float*)d_in[14]; const float* bc1 = (const float*)d_in[15];
    const float* Wc2 = (const float*)d_in[16]; const float* bc2 = (const float*)d_in[17];
    const float* Wa1 = (const float*)d_in[18]; const float* ba1 = (const float*)d_in[19];
    const float* Wa2 = (const float*)d_in[20]; const float* ba2 = (const float*)d_in[21];
    const float* Wb  = (const float*)d_in[22]; const float* bb  = (const float*)d_in[23];
    float* out = (float*)d_out;

    Scratch* s = nullptr;
    cudaGetSymbolAddress((void**)&s, g_s);

    cudaFuncSetAttribute(mma_scores_kernel,
                         cudaFuncAttributeMaxDynamicSharedMemorySize, SC_DYN);

    const int GN_D  = (D_ + 63) / 64;            // 29
    const int GN_4D = (4 * D_ + 127) / 128;      // 57
    const int GN_V  = V_ / 128;                  // 250
    const int CONV_BLK = (S_ * B_ * E_ / 8 + D_ * E_ / 8 + 255) / 256;  // 7172

    // 0. fp16 preconversion of h and Wa1 key-slice
    conv16_kernel<<<CONV_BLK, 256>>>(h, Wa1, s->h16, s->w16);

    // 1. encoder mean
    havg_kernel<<<dim3(B_, E_ / 256), 256>>>(h, s->havg);

    // 2. init-state layer1 -> partials (KS=2)
    {
        SKJob2 jj;
        jj.j[0] = {s->havg, nullptr, nullptr, nullptr, 0, Wh1, E_, E_, D_, s->skpA[0][0]};
        jj.j[1] = {s->havg, nullptr, nullptr, nullptr, 0, Wc1, E_, E_, D_, s->skpA[1][0]};
        sk_gemm_kernel<64><<<dim3(GN_D, 2, 2), 256>>>(jj);
    }
    // 3. layer2, A = relu(sum L1 partials + b1) fused (KS=3)
    {
        SKJob2 jj;
        jj.j[0] = {s->skpA[0][0], s->skpA[0][1], nullptr, bh1, 1, Wh2, D_, D_, D_, s->skpB[0][0]};
        jj.j[1] = {s->skpA[1][0], s->skpA[1][1], nullptr, bc1, 1, Wc2, D_, D_, D_, s->skpB[1][0]};
        sk_gemm_kernel<64><<<dim3(GN_D, 2, 3), 256>>>(jj);
    }
    // 4. qpart partials = (h0 = sum L2 partials + bh2) @ Wa1[:, :D]^T  (KS=3)
    {
        SKJob2 jj;
        jj.j[0] = {s->skpB[0][0], s->skpB[0][1], s->skpB[0][2], bh2, 0, Wa1, D_, DE_, D_, s->skpA[0][0]};
        jj.j[1] = jj.j[0];
        sk_gemm_kernel<64><<<dim3(GN_D, 1, 3), 256>>>(jj);
    }
    // 5. qpart reduce (+ ba1)
    sk_reduce3_kernel<<<(B_ * D_ + 255) / 256, 256>>>(s->skpA[0][0], ba1, s->qpart);

    // 6. fused scores GEMM (fp16, preconverted, materialized qpart)
    mma_scores_kernel<<<dim3(S_ / 4, 3), 256, SC_DYN>>>(
        s->h16, s->w16, s->qpart, Wa2, s->spart);

    // 7. argmax of y_tm1
    argmax_kernel<<<B_, 256>>>(y_tm1, s->amax);

    // 8. softmax + beta (h0 virtual from partials)
    float* aw_out = out + (size_t)B_ * V_ + 2 * (size_t)B_ * D_;
    softmax_beta_kernel<<<B_, 256>>>(s->spart, s->skpB[0][0], s->skpB[0][1], s->skpB[0][2],
                                     bh2, Wb, bb, ba2, aw_out, s->beta);

    // 9. context
    ctx_kernel<<<dim3(B_, E_ / 256), 256>>>(h, aw_out, s->beta, s->ctx);

    // 10. LSTM input + gates (h0 virtual in job1)
    xbuild_kernel<<<dim3(B_, WE_ / 256), 256>>>(emb, E_tm1, s->ctx, s->x);
    {
        SKJob2 jj;
        jj.j[0] = {s->x, nullptr, nullptr, nullptr, 0, W_ih, WE_, WE_, 4 * D_, s->gp0};
        jj.j[1] = {s->skpB[0][0], s->skpB[0][1], s->skpB[0][2], bh2, 0, W_hh, D_, D_, 4 * D_, s->gp1};
        sk_gemm_kernel<128><<<dim3(GN_4D, 2, 1), 256>>>(jj);
    }

    // 11. LSTM pointwise (c0 virtual from partials)
    lstm_kernel<<<dim3(B_, (D_ + 255) / 256), 256>>>(
        s->gp0, s->gp1, b_ih, b_hh,
        s->skpB[1][0], s->skpB[1][1], s->skpB[1][2], bc2, out, s->z);

    // 12. z tail
    zbuild_kernel<<<dim3(B_, WE_ / 256), 256>>>(emb, s->amax, s->ctx, s->z);

    // 13. logits
    logits_kernel<<<GN_V, 256>>>(s->z, W_out, b_out, out);
}

// round 12
// speedup vs baseline: 1.0759x; 1.0014x over previous
#include <cuda_runtime.h>
#include <cuda_fp16.h>
#include <math.h>
#include <stdint.h>

#define S_ 196
#define B_ 64
#define E_ 1024
#define D_ 1800
#define W_ 512
#define V_ 32000
#define WE_ (W_ + E_)       // 1536
#define DE_ (D_ + E_)       // 2824
#define DWE_ (D_ + W_ + E_) // 3336

// ---------------------------------------------------------------------------
// Scratch
// ---------------------------------------------------------------------------
struct Scratch {
    float havg[B_ * E_];
    float skpA[2][3][B_ * D_];
    float skpB[2][3][B_ * D_];
    float qpart[B_ * D_];
    float spart[3 * S_ * B_];
    float beta[B_];
    float ctx[B_ * E_];
    float x[B_ * WE_];
    float z[B_ * DWE_];
    float gp0[B_ * 4 * D_];
    float gp1[B_ * 4 * D_];
    int   amax[B_];
    __half h16[S_ * B_ * E_];   // fp16 copy of h
    __half w16[D_ * E_];        // fp16 copy of Wa1[:, D:]
};
__device__ Scratch g_s;

// ---------------------------------------------------------------------------
// fp16 MMA helpers
// ---------------------------------------------------------------------------
__device__ __forceinline__ uint32_t packh2(float a, float b) {
    __half2 h = __floats2half2_rn(a, b);
    return *(uint32_t*)&h;
}
__device__ __forceinline__ void mma_f16(float (&c)[4], const uint32_t (&a)[4],
                                        const uint32_t b0, const uint32_t b1) {
    asm volatile(
        "mma.sync.aligned.m16n8k16.row.col.f32.f16.f16.f32 "
        "{%0,%1,%2,%3},{%4,%5,%6,%7},{%8,%9},{%0,%1,%2,%3};"
        : "+f"(c[0]), "+f"(c[1]), "+f"(c[2]), "+f"(c[3])
        : "r"(a[0]), "r"(a[1]), "r"(a[2]), "r"(a[3]), "r"(b0), "r"(b1));
}
__device__ __forceinline__ void ldsm4(uint32_t (&r)[4], uint32_t addr) {
    asm volatile("ldmatrix.sync.aligned.m8n8.x4.shared.b16 {%0,%1,%2,%3}, [%4];"
        : "=r"(r[0]), "=r"(r[1]), "=r"(r[2]), "=r"(r[3]) : "r"(addr));
}
__device__ __forceinline__ void ldsm2(uint32_t (&r)[2], uint32_t addr) {
    asm volatile("ldmatrix.sync.aligned.m8n8.x2.shared.b16 {%0,%1}, [%2];"
        : "=r"(r[0]), "=r"(r[1]) : "r"(addr));
}
__device__ __forceinline__ void ld8(float* d, const float* p) {
    float4 a = ((const float4*)p)[0], b = ((const float4*)p)[1];
    d[0]=a.x; d[1]=a.y; d[2]=a.z; d[3]=a.w; d[4]=b.x; d[5]=b.y; d[6]=b.z; d[7]=b.w;
}
__device__ __forceinline__ void add8(float* d, const float* p) {
    float4 a = ((const float4*)p)[0], b = ((const float4*)p)[1];
    d[0]+=a.x; d[1]+=a.y; d[2]+=a.z; d[3]+=a.w; d[4]+=b.x; d[5]+=b.y; d[6]+=b.z; d[7]+=b.w;
}

// Row stride 20 uint32: 8-row base pattern {0,20,8,28,16,4,24,12} mod 32 ->
// conflict-free LDSM row fetches and STS.128 phases.
#define SPADH 20

// ---------------------------------------------------------------------------
// fp32 -> fp16 preconversion: h16 = h, w16 = Wa1[:, D:] (row stride E)
// ---------------------------------------------------------------------------
__global__ __launch_bounds__(256) void conv16_kernel(
    const float* __restrict__ h, const float* __restrict__ Wa1,
    __half* __restrict__ h16, __half* __restrict__ w16)
{
    const int HT = S_ * B_ * E_ / 8;       // octets in h
    const int WT = D_ * E_ / 8;            // octets in w16
    int idx = blockIdx.x * 256 + threadIdx.x;
    if (idx < HT) {
        const float4* p = (const float4*)(h + (size_t)idx * 8);
        float4 a = p[0], b = p[1];
        *(uint4*)(h16 + (size_t)idx * 8) =
            make_uint4(packh2(a.x, a.y), packh2(a.z, a.w),
                       packh2(b.x, b.y), packh2(b.z, b.w));
    } else if (idx - HT < WT) {
        int j = idx - HT;
        int n = j / (E_ / 8), k8 = j % (E_ / 8);
        const float4* p = (const float4*)(Wa1 + (size_t)n * DE_ + D_ + k8 * 8);
        float4 a = p[0], b = p[1];
        *(uint4*)(w16 + (size_t)n * E_ + k8 * 8) =
            make_uint4(packh2(a.x, a.y), packh2(a.z, a.w),
                       packh2(b.x, b.y), packh2(b.z, b.w));
    }
}

// ---------------------------------------------------------------------------
// Small-GEMM K-segment, fp16 MMA, fused A-side reduce
// ---------------------------------------------------------------------------
struct SKJob {
    const float* A0; const float* A1p; const float* A2p;
    const float* kb; int krelu;
    const float* W; int K; int ldw; int N; float* Cpart;
};
struct SKJob2 { SKJob j[2]; };

template<int BN>
__device__ __forceinline__ void seg64(
    const SKJob& j, const int nb, const int t0, const int t1,
    uint32_t As[64][SPADH], uint32_t Ws[BN][SPADH],
    float (&acc)[2][BN / 32][4])
{
    constexpr int NF  = BN / 32;
    constexpr int WPT = (BN == 64) ? 8 : 16;
    const int tid  = threadIdx.x;
    const int lane = tid & 31, wid = tid >> 5;
    const int warpM = wid >> 2, warpN = wid & 3;

    const int am  = tid & 63, akg = (tid >> 6) * 8;
    const int wn  = (BN == 64) ? (tid & 63) : (tid & 127);
    const int wkg = (BN == 64) ? ((tid >> 6) * 8) : ((tid >> 7) * 16);
    const bool wvalid = (nb + wn) < j.N;
    const int K = j.K;
    const float* A0r = j.A0 + (size_t)am * K;
    const float* A1r = j.A1p ? j.A1p + (size_t)am * K : nullptr;
    const float* A2r = j.A2p ? j.A2p + (size_t)am * K : nullptr;
    const float* Wbase = j.W + (size_t)(nb + wn) * j.ldw;

    uint32_t aAddr[2][2], bAddr[NF];
    #pragma unroll
    for (int mf = 0; mf < 2; mf++)
        #pragma unroll
        for (int ks = 0; ks < 2; ks++)
            aAddr[mf][ks] = (uint32_t)__cvta_generic_to_shared(
                &As[warpM * 32 + mf * 16 + (lane & 15)][ks * 8 + 4 * (lane >> 4)]);
    #pragma unroll
    for (int nf = 0; nf < NF; nf++)
        bAddr[nf] = (uint32_t)__cvta_generic_to_shared(
            &Ws[warpN * (BN / 4) + nf * 8 + (lane & 7)][4 * (lane >> 3)]);

    float ra[8], rw[WPT];

    auto loadA = [&](int ti) {
        const int k0 = ti * 32 + akg;
        if (k0 + 8 <= K) {
            ld8(ra, A0r + k0);
            if (A1r) add8(ra, A1r + k0);
            if (A2r) add8(ra, A2r + k0);
            if (j.kb) add8(ra, j.kb + k0);
        } else {
            #pragma unroll
            for (int i = 0; i < 8; i++) {
                int k = k0 + i; float v = 0.f;
                if (k < K) {
                    v = A0r[k];
                    if (A1r) v += A1r[k];
                    if (A2r) v += A2r[k];
                    if (j.kb) v += j.kb[k];
                }
                ra[i] = v;
            }
        }
        if (j.krelu) {
            #pragma unroll
            for (int i = 0; i < 8; i++) ra[i] = fmaxf(ra[i], 0.f);
        }
    };
    auto loadW = [&](int ti) {
        const int k0 = ti * 32 + wkg;
        if (wvalid && k0 + WPT <= K) {
            #pragma unroll
            for (int i = 0; i < WPT / 4; i++) {
                float4 v = *(const float4*)(Wbase + k0 + i * 4);
                rw[i*4+0]=v.x; rw[i*4+1]=v.y; rw[i*4+2]=v.z; rw[i*4+3]=v.w;
            }
        } else {
            #pragma unroll
            for (int i = 0; i < WPT; i++)
                rw[i] = (wvalid && (k0 + i) < K) ? Wbase[k0 + i] : 0.f;
        }
    };

    loadA(t0);
    loadW(t0);

    for (int ti = t0; ti < t1; ti++) {
        __syncthreads();
        *(uint4*)&As[am][akg >> 1] =
            make_uint4(packh2(ra[0], ra[1]), packh2(ra[2], ra[3]),
                       packh2(ra[4], ra[5]), packh2(ra[6], ra[7]));
        #pragma unroll
        for (int h8 = 0; h8 < WPT / 8; h8++) {
            const float* r = rw + h8 * 8;
            *(uint4*)&Ws[wn][(wkg >> 1) + h8 * 4] =
                make_uint4(packh2(r[0], r[1]), packh2(r[2], r[3]),
                           packh2(r[4], r[5]), packh2(r[6], r[7]));
        }
        __syncthreads();

        if (ti + 1 < t1) { loadA(ti + 1); loadW(ti + 1); }

        uint32_t b[NF][4];
        #pragma unroll
        for (int nf = 0; nf < NF; nf++) ldsm4(b[nf], bAddr[nf]);
        #pragma unroll
        for (int ks = 0; ks < 2; ks++) {
            uint32_t a[2][4];
            ldsm4(a[0], aAddr[0][ks]);
            ldsm4(a[1], aAddr[1][ks]);
            #pragma unroll
            for (int nf = 0; nf < NF; nf++) {
                mma_f16(acc[0][nf], a[0], b[nf][2 * ks], b[nf][2 * ks + 1]);
                mma_f16(acc[1][nf], a[1], b[nf][2 * ks], b[nf][2 * ks + 1]);
            }
        }
    }
}

template<int BN>
__global__ __launch_bounds__(256) void sk_gemm_kernel(SKJob2 jobs)
{
    constexpr int NF = BN / 32;
    __shared__ __align__(16) uint32_t As[64][SPADH];
    __shared__ __align__(16) uint32_t Ws[BN][SPADH];

    const SKJob j = jobs.j[blockIdx.y];
    const int nb = blockIdx.x * BN;
    if (nb >= j.N) return;

    const int tiles = (j.K + 31) >> 5;
    const int KS = gridDim.z, kz = blockIdx.z;
    const int tpk = (tiles + KS - 1) / KS;
    const int t0 = kz * tpk;
    const int t1 = (t0 + tpk < tiles) ? (t0 + tpk) : tiles;

    float acc[2][NF][4] = {};
    if (t0 < t1)
        seg64<BN>(j, nb, t0, t1, As, Ws, acc);

    float* C = j.Cpart + (size_t)kz * 64 * j.N;
    const int tid = threadIdx.x, lane = tid & 31, wid = tid >> 5;
    const int warpM = wid >> 2, warpN = wid & 3;
    const int g = lane >> 2, t = lane & 3;

    #pragma unroll
    for (int mf = 0; mf < 2; mf++) {
        const int row = warpM * 32 + mf * 16 + g;
        #pragma unroll
        for (int nf = 0; nf < NF; nf++) {
            const int col = nb + warpN * (BN / 4) + nf * 8 + 2 * t;
            if (col < j.N) {
                *(float2*)&C[(size_t)row * j.N + col]       = make_float2(acc[mf][nf][0], acc[mf][nf][1]);
                *(float2*)&C[(size_t)(row + 8) * j.N + col] = make_float2(acc[mf][nf][2], acc[mf][nf][3]);
            }
        }
    }
}

// qpart reduce: 3 partials + bias
__global__ __launch_bounds__(256) void sk_reduce3_kernel(
    const float* __restrict__ part, const float* __restrict__ bias,
    float* __restrict__ outp)
{
    int idx = blockIdx.x * 256 + threadIdx.x;
    if (idx >= B_ * D_) return;
    int n = idx % D_;
    float v = bias[n] + part[idx] + part[(size_t)B_ * D_ + idx] + part[2 * (size_t)B_ * D_ + idx];
    outp[idx] = v;
}

__global__ __launch_bounds__(256) void logits_kernel(
    const float* __restrict__ z, const float* __restrict__ Wt,
    const float* __restrict__ bias, float* __restrict__ C)
{
    __shared__ __align__(16) uint32_t As[64][SPADH];
    __shared__ __align__(16) uint32_t Ws[128][SPADH];

    SKJob j; j.A0 = z; j.A1p = nullptr; j.A2p = nullptr; j.kb = nullptr; j.krelu = 0;
    j.W = Wt; j.K = DWE_; j.ldw = DWE_; j.N = V_; j.Cpart = nullptr;
    const int nb = blockIdx.x * 128;

    float acc[2][4][4] = {};
    seg64<128>(j, nb, 0, (DWE_ + 31) >> 5, As, Ws, acc);

    const int tid = threadIdx.x, lane = tid & 31, wid = tid >> 5;
    const int warpM = wid >> 2, warpN = wid & 3;
    const int g = lane >> 2, t = lane & 3;

    #pragma unroll
    for (int mf = 0; mf < 2; mf++) {
        const int row = warpM * 32 + mf * 16 + g;
        #pragma unroll
        for (int nf = 0; nf < 4; nf++) {
            const int col = nb + warpN * 32 + nf * 8 + 2 * t;
            float b0 = bias[col], b1 = bias[col + 1];
            *(float2*)&C[(size_t)row * V_ + col]       = make_float2(acc[mf][nf][0] + b0, acc[mf][nf][1] + b1);
            *(float2*)&C[(size_t)(row + 8) * V_ + col] = make_float2(acc[mf][nf][2] + b0, acc[mf][nf][3] + b1);
        }
    }
}

// ---------------------------------------------------------------------------
// Fused attention scores: preconverted fp16 inputs, ktile=32, ping-pong
// dynamic smem (1 sync/iter), materialized qpart in epilogue.
// BM=256 (4 seq), BN=128, 8 warps (4M x 2N), warp tile 64x64. grid = (49, 3).
// ---------------------------------------------------------------------------
#define SPH2 20
#define AS_WORDS (256 * SPH2)
#define WS_WORDS (128 * SPH2)
#define SC_DYN ((2 * AS_WORDS + 2 * WS_WORDS) * 4)   // 61440 B

__global__ __launch_bounds__(256, 1) void mma_scores_kernel(
    const __half* __restrict__ h16, const __half* __restrict__ w16,
    const float* __restrict__ qpart, const float* __restrict__ Wa2,
    float* __restrict__ spart)
{
    extern __shared__ uint32_t dyn[];
    uint32_t (*As)[256][SPH2] = (uint32_t(*)[256][SPH2])dyn;
    uint32_t (*Ws)[128][SPH2] = (uint32_t(*)[128][SPH2])(dyn + 2 * AS_WORDS);

    const int tid = threadIdx.x, lane = tid & 31, wid = tid >> 5;
    const int warpM = wid >> 1, warpN = wid & 1;
    const int g = lane >> 2, t = lane & 3;

    const __half* Abase = h16 + ((size_t)blockIdx.x * 256 + tid) * E_;
    const int wrow = tid & 127;
    const bool wldr = (tid < 128);

    const uint32_t ASO = AS_WORDS * 4, WSO = WS_WORDS * 4;
    uint32_t aA[4], bA[8];
    #pragma unroll
    for (int mf = 0; mf < 4; mf++)
        aA[mf] = (uint32_t)__cvta_generic_to_shared(
            &As[0][warpM * 64 + mf * 16 + (lane & 15)][4 * (lane >> 4)]);
    #pragma unroll
    for (int nf = 0; nf < 8; nf++)
        bA[nf] = (uint32_t)__cvta_generic_to_shared(
            &Ws[0][warpN * 64 + nf * 8 + (lane & 7)][4 * ((lane >> 3) & 1)]);

    float sacc[4][2] = {};

    const int tile0 = blockIdx.y * 5;
    for (int tile = tile0; tile < tile0 + 5; tile++) {
        const int nb = tile * 128;
        const bool wv = wldr && (nb + wrow) < D_;
        const __half* Wbase = w16 + (size_t)(nb + wrow) * E_;

        uint4 ra[4], rw[4];
        float acc[4][8][4] = {};

        auto loadA = [&](int ti) {
            const uint4* p = (const uint4*)(Abase + ti * 32);
            ra[0] = p[0]; ra[1] = p[1]; ra[2] = p[2]; ra[3] = p[3];
        };
        auto loadW = [&](int ti) {
            if (wv) {
                const uint4* p = (const uint4*)(Wbase + ti * 32);
                rw[0] = p[0]; rw[1] = p[1]; rw[2] = p[2]; rw[3] = p[3];
            } else if (wldr) {
                rw[0] = rw[1] = rw[2] = rw[3] = make_uint4(0, 0, 0, 0);
            }
        };
        auto stsAB = [&](int buf) {
            uint4* pa = (uint4*)&As[buf][tid][0];
            pa[0] = ra[0]; pa[1] = ra[1]; pa[2] = ra[2]; pa[3] = ra[3];
            if (wldr) {
                uint4* pw = (uint4*)&Ws[buf][wrow][0];
                pw[0] = rw[0]; pw[1] = rw[1]; pw[2] = rw[2]; pw[3] = rw[3];
            }
        };
        auto domma = [&](int buf) {
            const uint32_t ao = buf * ASO, wo = buf * WSO;
            #pragma unroll
            for (int ks = 0; ks < 2; ks++) {
                uint32_t b[8][2];
                #pragma unroll
                for (int nf = 0; nf < 8; nf++) ldsm2(b[nf], bA[nf] + wo + ks * 32);
                #pragma unroll
                for (int mf = 0; mf < 4; mf++) {
                    uint32_t a[4];
                    ldsm4(a, aA[mf] + ao + ks * 32);
                    #pragma unroll
                    for (int nf = 0; nf < 8; nf++)
                        mma_f16(acc[mf][nf], a, b[nf][0], b[nf][1]);
                }
            }
        };

        loadA(0); loadW(0);
        __syncthreads();
        stsAB(0);
        loadA(1); loadW(1);

        for (int ti = 0; ti < E_ / 32; ti++) {
            __syncthreads();
            if (ti + 1 < E_ / 32) stsAB((ti + 1) & 1);
            if (ti + 2 < E_ / 32) { loadA(ti + 2); loadW(ti + 2); }
            domma(ti & 1);
        }

        // epilogue: + qpart, relu, * Wa2, accumulate per-row
        #pragma unroll
        for (int mf = 0; mf < 4; mf++) {
            const int r0 = warpM * 64 + mf * 16 + g;
            const int b0 = r0 & 63, b1 = (r0 + 8) & 63;
            #pragma unroll
            for (int nf = 0; nf < 8; nf++) {
                const int col = nb + warpN * 64 + nf * 8 + 2 * t;
                if (col < D_) {
                    float2 w  = *(const float2*)(Wa2 + col);
                    float2 q0 = *(const float2*)(qpart + (size_t)b0 * D_ + col);
                    float2 q1 = *(const float2*)(qpart + (size_t)b1 * D_ + col);
                    sacc[mf][0] += fmaxf(acc[mf][nf][0] + q0.x, 0.f) * w.x
                                 + fmaxf(acc[mf][nf][1] + q0.y, 0.f) * w.y;
                    sacc[mf][1] += fmaxf(acc[mf][nf][2] + q1.x, 0.f) * w.x
                                 + fmaxf(acc[mf][nf][3] + q1.y, 0.f) * w.y;
                }
            }
        }
    }

    __syncthreads();
    float* red = (float*)dyn;        // [256][9] overlay
    #pragma unroll
    for (int mf = 0; mf < 4; mf++) {
        const int r0 = warpM * 64 + mf * 16 + g;
        red[r0 * 9 + warpN * 4 + t]       = sacc[mf][0];
        red[(r0 + 8) * 9 + warpN * 4 + t] = sacc[mf][1];
    }
    __syncthreads();
    {
        const int row = tid;
        float a = 0.f;
        #pragma unroll
        for (int c = 0; c < 8; c++) a += red[row * 9 + c];
        const int s = blockIdx.x * 4 + (row >> 6);
        const int b = row & 63;
        spart[(size_t)blockIdx.y * S_ * B_ + (size_t)s * B_ + b] = a;
    }
}

// ---------------------------------------------------------------------------
// Small kernels (unchanged)
// ---------------------------------------------------------------------------
__global__ void havg_kernel(const float* __restrict__ h, float* __restrict__ havg)
{
    int b = blockIdx.x;
    int e = blockIdx.y * 256 + threadIdx.x;
    float s = 0.f;
    for (int si = 0; si < S_; si++)
        s += h[((size_t)si * B_ + b) * E_ + e];
    havg[(size_t)b * E_ + e] = s * (1.f / (float)S_);
}

__global__ __launch_bounds__(256) void softmax_beta_kernel(
    const float* __restrict__ spart,
    const float* __restrict__ hp0, const float* __restrict__ hp1,
    const float* __restrict__ hp2, const float* __restrict__ bh2,
    const float* __restrict__ Wb, const float* __restrict__ bb,
    const float* __restrict__ ba2,
    float* __restrict__ aw_out, float* __restrict__ beta)
{
    int b = blockIdx.x, tid = threadIdx.x;
    __shared__ float sm[256];

    float p = 0.f;
    for (int d = tid; d < D_; d += 256) {
        size_t i = (size_t)b * D_ + d;
        float hv = hp0[i] + hp1[i] + hp2[i] + bh2[d];
        p = fmaf(hv, Wb[d], p);
    }
    sm[tid] = p; __syncthreads();
    for (int o = 128; o > 0; o >>= 1) { if (tid < o) sm[tid] += sm[tid + o]; __syncthreads(); }
    if (tid == 0) beta[b] = 1.f / (1.f + expf(-(sm[0] + bb[0])));
    __syncthreads();

    float v = -3.4e38f;
    if (tid < S_) {
        size_t idx = (size_t)tid * B_ + b;
        v = spart[idx] + spart[(size_t)S_ * B_ + idx] + spart[2 * (size_t)S_ * B_ + idx] + ba2[0];
    }
    sm[tid] = v; __syncthreads();
    for (int o = 128; o > 0; o >>= 1) { if (tid < o) sm[tid] = fmaxf(sm[tid], sm[tid + o]); __syncthreads(); }
    float mx = sm[0]; __syncthreads();
    float e = (tid < S_) ? expf(v - mx) : 0.f;
    sm[tid] = e; __syncthreads();
    for (int o = 128; o > 0; o >>= 1) { if (tid < o) sm[tid] += sm[tid + o]; __syncthreads(); }
    float inv = 1.f / sm[0];
    if (tid < S_) aw_out[(size_t)tid * B_ + b] = e * inv;
}

__global__ void ctx_kernel(const float* __restrict__ h, const float* __restrict__ aw,
                           const float* __restrict__ beta, float* __restrict__ ctx)
{
    int b = blockIdx.x;
    int e = blockIdx.y * 256 + threadIdx.x;
    float s = 0.f;
    for (int si = 0; si < S_; si++)
        s = fmaf(aw[(size_t)si * B_ + b], h[((size_t)si * B_ + b) * E_ + e], s);
    ctx[(size_t)b * E_ + e] = s * beta[b];
}

__global__ __launch_bounds__(256) void argmax_kernel(const float* __restrict__ y, int* __restrict__ amax)
{
    int b = blockIdx.x, tid = threadIdx.x;
    float bm = -3.4e38f; int bi = 0;
    for (int i = tid; i < V_; i += 256) {
        float v = y[(size_t)b * V_ + i];
        if (v > bm) { bm = v; bi = i; }
    }
    __shared__ float sv[256];
    __shared__ int si_[256];
    sv[tid] = bm; si_[tid] = bi; __syncthreads();
    for (int o = 128; o > 0; o >>= 1) {
        if (tid < o) {
            if (sv[tid + o] > sv[tid] || (sv[tid + o] == sv[tid] && si_[tid + o] < si_[tid])) {
                sv[tid] = sv[tid + o]; si_[tid] = si_[tid + o];
            }
        }
        __syncthreads();
    }
    if (tid == 0) amax[b] = si_[0];
}

__global__ void xbuild_kernel(const float* __restrict__ emb, const int* __restrict__ Etm1,
                              const float* __restrict__ ctx, float* __restrict__ x)
{
    int b = blockIdx.x;
    int i = blockIdx.y * 256 + threadIdx.x;
    if (i < W_) x[(size_t)b * WE_ + i] = emb[(size_t)Etm1[b] * W_ + i];
    else        x[(size_t)b * WE_ + i] = ctx[(size_t)b * E_ + (i - W_)];
}

__global__ void lstm_kernel(const float* __restrict__ gp0, const float* __restrict__ gp1,
                            const float* __restrict__ b_ih, const float* __restrict__ b_hh,
                            const float* __restrict__ cp0, const float* __restrict__ cp1,
                            const float* __restrict__ cp2, const float* __restrict__ bc2,
                            float* __restrict__ out, float* __restrict__ z)
{
    int b = blockIdx.x;
    int d = blockIdx.y * 256 + threadIdx.x;
    if (d >= D_) return;
    const size_t base = (size_t)b * 4 * D_;
    float gi = gp0[base + d]          + gp1[base + d]          + b_ih[d]          + b_hh[d];
    float gf = gp0[base + D_ + d]     + gp1[base + D_ + d]     + b_ih[D_ + d]     + b_hh[D_ + d];
    float gg = gp0[base + 2*D_ + d]   + gp1[base + 2*D_ + d]   + b_ih[2*D_ + d]   + b_hh[2*D_ + d];
    float go = gp0[base + 3*D_ + d]   + gp1[base + 3*D_ + d]   + b_ih[3*D_ + d]   + b_hh[3*D_ + d];
    size_t ci = (size_t)b * D_ + d;
    float c0 = cp0[ci] + cp1[ci] + cp2[ci] + bc2[d];
    float ig = 1.f / (1.f + expf(-gi));
    float fg = 1.f / (1.f + expf(-gf));
    float gt = tanhf(gg);
    float og = 1.f / (1.f + expf(-go));
    float c = fmaf(fg, c0, ig * gt);
    float ht = og * tanhf(c);
    out[(size_t)B_ * V_ + (size_t)b * D_ + d] = ht;
    out[(size_t)B_ * V_ + (size_t)B_ * D_ + (size_t)b * D_ + d] = c;
    z[(size_t)b * DWE_ + d] = ht;
}

__global__ void zbuild_kernel(const float* __restrict__ emb, const int* __restrict__ amax,
                              const float* __restrict__ ctx, float* __restrict__ z)
{
    int b = blockIdx.x;
    int i = blockIdx.y * 256 + threadIdx.x;
    if (i < W_) z[(size_t)b * DWE_ + D_ + i] = emb[(size_t)amax[b] * W_ + i];
    else        z[(size_t)b * DWE_ + D_ + i] = ctx[(size_t)b * E_ + (i - W_)];
}

// ---------------------------------------------------------------------------
// Launch
// ---------------------------------------------------------------------------
extern "C" void kernel_launch(void* const* d_in, const int* in_sizes, int n_in,
                              void* d_out, int out_size)
{
    const int*   E_tm1 = (const int*)d_in[0];
    const float* y_tm1 = (const float*)d_in[1];
    const float* h     = (const float*)d_in[2];
    const float* emb   = (const float*)d_in[3];
    const float* W_ih  = (const float*)d_in[4];
    const float* b_ih  = (const float*)d_in[5];
    const float* W_hh  = (const float*)d_in[6];
    const float* b_hh  = (const float*)d_in[7];
    const float* W_out = (const float*)d_in[8];
    const float* b_out = (const float*)d_in[9];
    const float* Wh1 = (const float*)d_in[10]; const float* bh1 = (const float*)d_in[11];
    const float* Wh2 = (const float*)d_in[12]; const float* bh2 = (const float*)d_in[13];
    const float* Wc1 = (const float*)d_in[14]; const float* bc1 = (const float*)d_in[15];
    const float* Wc2 = (const float*)d_in[16]; const float* bc2 = (const float*)d_in[17];
    const float* Wa1 = (const float*)d_in[18]; const float* ba1 = (const float*)d_in[19];
    const float* Wa2 = (const float*)d_in[20]; const float* ba2 = (const float*)d_in[21];
    const float* Wb  = (const float*)d_in[22]; const float* bb  = (const float*)d_in[23];
    float* out = (float*)d_out;

    Scratch* s = nullptr;
    cudaGetSymbolAddress((void**)&s, g_s);

    cudaFuncSetAttribute(mma_scores_kernel,
                         cudaFuncAttributeMaxDynamicSharedMemorySize, SC_DYN);

    const int GN_D  = (D_ + 63) / 64;            // 29
    const int GN_4D = (4 * D_ + 127) / 128;      // 57
    const int GN_V  = V_ / 128;                  // 250
    const int CONV_BLK = (S_ * B_ * E_ / 8 + D_ * E_ / 8 + 255) / 256;  // 7172

    // 0. fp16 preconversion of h and Wa1 key-slice
    conv16_kernel<<<CONV_BLK, 256>>>(h, Wa1, s->h16, s->w16);

    // 1. encoder mean
    havg_kernel<<<dim3(B_, E_ / 256), 256>>>(h, s->havg);

    // 2. init-state layer1 -> partials (KS=2)
    {
        SKJob2 jj;
        jj.j[0] = {s->havg, nullptr, nullptr, nullptr, 0, Wh1, E_, E_, D_, s->skpA[0][0]};
        jj.j[1] = {s->havg, nullptr, nullptr, nullptr, 0, Wc1, E_, E_, D_, s->skpA[1][0]};
        sk_gemm_kernel<64><<<dim3(GN_D, 2, 2), 256>>>(jj);
    }
    // 3. layer2, A = relu(sum L1 partials + b1) fused (KS=3)
    {
        SKJob2 jj;
        jj.j[0] = {s->skpA[0][0], s->skpA[0][1], nullptr, bh1, 1, Wh2, D_, D_, D_, s->skpB[0][0]};
        jj.j[1] = {s->skpA[1][0], s->skpA[1][1], nullptr, bc1, 1, Wc2, D_, D_, D_, s->skpB[1][0]};
        sk_gemm_kernel<64><<<dim3(GN_D, 2, 3), 256>>>(jj);
    }
    // 4. qpart partials = (h0 = sum L2 partials + bh2) @ Wa1[:, :D]^T  (KS=3)
    {
        SKJob2 jj;
        jj.j[0] = {s->skpB[0][0], s->skpB[0][1], s->skpB[0][2], bh2, 0, Wa1, D_, DE_, D_, s->skpA[0][0]};
        jj.j[1] = jj.j[0];
        sk_gemm_kernel<64><<<dim3(GN_D, 1, 3), 256>>>(jj);
    }
    // 5. qpart reduce (+ ba1)
    sk_reduce3_kernel<<<(B_ * D_ + 255) / 256, 256>>>(s->skpA[0][0], ba1, s->qpart);

    // 6. fused scores GEMM (fp16, preconverted, materialized qpart)
    mma_scores_kernel<<<dim3(S_ / 4, 3), 256, SC_DYN>>>(
        s->h16, s->w16, s->qpart, Wa2, s->spart);

    // 7. argmax of y_tm1
    argmax_kernel<<<B_, 256>>>(y_tm1, s->amax);

    // 8. softmax + beta (h0 virtual from partials)
    float* aw_out = out + (size_t)B_ * V_ + 2 * (size_t)B_ * D_;
    softmax_beta_kernel<<<B_, 256>>>(s->spart, s->skpB[0][0], s->skpB[0][1], s->skpB[0][2],
                                     bh2, Wb, bb, ba2, aw_out, s->beta);

    // 9. context
    ctx_kernel<<<dim3(B_, E_ / 256), 256>>>(h, aw_out, s->beta, s->ctx);

    // 10. LSTM input + gates (h0 virtual in job1)
    xbuild_kernel<<<dim3(B_, WE_ / 256), 256>>>(emb, E_tm1, s->ctx, s->x);
    {
        SKJob2 jj;
        jj.j[0] = {s->x, nullptr, nullptr, nullptr, 0, W_ih, WE_, WE_, 4 * D_, s->gp0};
        jj.j[1] = {s->skpB[0][0], s->skpB[0][1], s->skpB[0][2], bh2, 0, W_hh, D_, D_, 4 * D_, s->gp1};
        sk_gemm_kernel<128><<<dim3(GN_4D, 2, 1), 256>>>(jj);
    }

    // 11. LSTM pointwise (c0 virtual from partials)
    lstm_kernel<<<dim3(B_, (D_ + 255) / 256), 256>>>(
        s->gp0, s->gp1, b_ih, b_hh,
        s->skpB[1][0], s->skpB[1][1], s->skpB[1][2], bc2, out, s->z);

    // 12. z tail
    zbuild_kernel<<<dim3(B_, WE_ / 256), 256>>>(emb, s->amax, s->ctx, s->z);

    // 13. logits
    logits_kernel<<<GN_V, 256>>>(s->z, W_out, b_out, out);
}

// round 13
// speedup vs baseline: 1.1090x; 1.0308x over previous
#include <cuda_runtime.h>
#include <cuda_fp16.h>
#include <math.h>
#include <stdint.h>

#define S_ 196
#define B_ 64
#define E_ 1024
#define D_ 1800
#define W_ 512
#define V_ 32000
#define WE_ (W_ + E_)       // 1536
#define DE_ (D_ + E_)       // 2824
#define DWE_ (D_ + W_ + E_) // 3336

// ---------------------------------------------------------------------------
// Scratch
// ---------------------------------------------------------------------------
struct Scratch {
    float havg[B_ * E_];
    float skpA[2][3][B_ * D_];
    float skpB[2][3][B_ * D_];
    float qpart[B_ * D_];
    float spart[3 * S_ * B_];
    float beta[B_];
    float ctx[B_ * E_];
    float x[B_ * WE_];
    float z[B_ * DWE_];
    float gp0[2][B_ * 4 * D_];
    float gp1[2][B_ * 4 * D_];
    float lgp[2][B_ * V_];
    int   amax[B_];
    __half h16[S_ * B_ * E_];   // fp16 copy of h
    __half w16[D_ * E_];        // fp16 copy of Wa1[:, D:]
};
__device__ Scratch g_s;

// ---------------------------------------------------------------------------
// fp16 MMA helpers
// ---------------------------------------------------------------------------
__device__ __forceinline__ uint32_t packh2(float a, float b) {
    __half2 h = __floats2half2_rn(a, b);
    return *(uint32_t*)&h;
}
__device__ __forceinline__ void mma_f16(float (&c)[4], const uint32_t (&a)[4],
                                        const uint32_t b0, const uint32_t b1) {
    asm volatile(
        "mma.sync.aligned.m16n8k16.row.col.f32.f16.f16.f32 "
        "{%0,%1,%2,%3},{%4,%5,%6,%7},{%8,%9},{%0,%1,%2,%3};"
        : "+f"(c[0]), "+f"(c[1]), "+f"(c[2]), "+f"(c[3])
        : "r"(a[0]), "r"(a[1]), "r"(a[2]), "r"(a[3]), "r"(b0), "r"(b1));
}
__device__ __forceinline__ void ldsm4(uint32_t (&r)[4], uint32_t addr) {
    asm volatile("ldmatrix.sync.aligned.m8n8.x4.shared.b16 {%0,%1,%2,%3}, [%4];"
        : "=r"(r[0]), "=r"(r[1]), "=r"(r[2]), "=r"(r[3]) : "r"(addr));
}
__device__ __forceinline__ void ldsm4p(uint32_t* r, uint32_t addr) {
    asm volatile("ldmatrix.sync.aligned.m8n8.x4.shared.b16 {%0,%1,%2,%3}, [%4];"
        : "=r"(r[0]), "=r"(r[1]), "=r"(r[2]), "=r"(r[3]) : "r"(addr));
}
__device__ __forceinline__ void ldsm2(uint32_t (&r)[2], uint32_t addr) {
    asm volatile("ldmatrix.sync.aligned.m8n8.x2.shared.b16 {%0,%1}, [%2];"
        : "=r"(r[0]), "=r"(r[1]) : "r"(addr));
}
__device__ __forceinline__ void ld8(float* d, const float* p) {
    float4 a = ((const float4*)p)[0], b = ((const float4*)p)[1];
    d[0]=a.x; d[1]=a.y; d[2]=a.z; d[3]=a.w; d[4]=b.x; d[5]=b.y; d[6]=b.z; d[7]=b.w;
}
__device__ __forceinline__ void add8(float* d, const float* p) {
    float4 a = ((const float4*)p)[0], b = ((const float4*)p)[1];
    d[0]+=a.x; d[1]+=a.y; d[2]+=a.z; d[3]+=a.w; d[4]+=b.x; d[5]+=b.y; d[6]+=b.z; d[7]+=b.w;
}

// ktile=64: row stride 36 words (64 halves + 4 pad). Row bases 4r mod 32 ->
// conflict-free ldmatrix row fetches and STS.128 phases.
#define SPADH 36

// ---------------------------------------------------------------------------
// fp32 -> fp16 preconversion: h16 = h, w16 = Wa1[:, D:] (row stride E)
// ---------------------------------------------------------------------------
__global__ __launch_bounds__(256) void conv16_kernel(
    const float* __restrict__ h, const float* __restrict__ Wa1,
    __half* __restrict__ h16, __half* __restrict__ w16)
{
    const int HT = S_ * B_ * E_ / 8;
    const int WT = D_ * E_ / 8;
    int idx = blockIdx.x * 256 + threadIdx.x;
    if (idx < HT) {
        const float4* p = (const float4*)(h + (size_t)idx * 8);
        float4 a = p[0], b = p[1];
        *(uint4*)(h16 + (size_t)idx * 8) =
            make_uint4(packh2(a.x, a.y), packh2(a.z, a.w),
                       packh2(b.x, b.y), packh2(b.z, b.w));
    } else if (idx - HT < WT) {
        int j = idx - HT;
        int n = j / (E_ / 8), k8 = j % (E_ / 8);
        const float4* p = (const float4*)(Wa1 + (size_t)n * DE_ + D_ + k8 * 8);
        float4 a = p[0], b = p[1];
        *(uint4*)(w16 + (size_t)n * E_ + k8 * 8) =
            make_uint4(packh2(a.x, a.y), packh2(a.z, a.w),
                       packh2(b.x, b.y), packh2(b.z, b.w));
    }
}

// ---------------------------------------------------------------------------
// Small-GEMM K-segment, fp16 MMA, ktile=64, fused A-side reduce
// ---------------------------------------------------------------------------
struct SKJob {
    const float* A0; const float* A1p; const float* A2p;
    const float* kb; int krelu;
    const float* W; int K; int ldw; int N; float* Cpart;
};
struct SKJob2 { SKJob j[2]; };

template<int BN>
__device__ __forceinline__ void seg64(
    const SKJob& j, const int nb, const int t0, const int t1,
    uint32_t As[64][SPADH], uint32_t Ws[BN][SPADH],
    float (&acc)[2][BN / 32][4])
{
    constexpr int NF  = BN / 32;
    constexpr int WFT = (BN == 64) ? 16 : 32;   // W floats per thread
    const int tid  = threadIdx.x;
    const int lane = tid & 31, wid = tid >> 5;
    const int warpM = wid >> 2, warpN = wid & 3;

    const int am  = tid & 63, akg = (tid >> 6) * 16;
    const int wn  = (BN == 64) ? (tid & 63) : (tid & 127);
    const int wkg = (BN == 64) ? ((tid >> 6) * 16) : ((tid >> 7) * 32);
    const bool wvalid = (nb + wn) < j.N;
    const int K = j.K;
    const float* A0r = j.A0 + (size_t)am * K;
    const float* A1r = j.A1p ? j.A1p + (size_t)am * K : nullptr;
    const float* A2r = j.A2p ? j.A2p + (size_t)am * K : nullptr;
    const float* Wbase = j.W + (size_t)(nb + wn) * j.ldw;

    uint32_t aAddr[2][4], bAddr[NF][2];
    #pragma unroll
    for (int mf = 0; mf < 2; mf++)
        #pragma unroll
        for (int ks = 0; ks < 4; ks++)
            aAddr[mf][ks] = (uint32_t)__cvta_generic_to_shared(
                &As[warpM * 32 + mf * 16 + (lane & 15)][ks * 8 + 4 * (lane >> 4)]);
    #pragma unroll
    for (int nf = 0; nf < NF; nf++)
        #pragma unroll
        for (int hh = 0; hh < 2; hh++)
            bAddr[nf][hh] = (uint32_t)__cvta_generic_to_shared(
                &Ws[warpN * (BN / 4) + nf * 8 + (lane & 7)][hh * 16 + 4 * (lane >> 3)]);

    float ra[16], rw[WFT];

    auto loadA = [&](int ti) {
        #pragma unroll
        for (int g = 0; g < 2; g++) {
            const int k0 = ti * 64 + akg + g * 8;
            float* d = ra + g * 8;
            if (k0 + 8 <= K) {
                ld8(d, A0r + k0);
                if (A1r) add8(d, A1r + k0);
                if (A2r) add8(d, A2r + k0);
                if (j.kb) add8(d, j.kb + k0);
            } else {
                #pragma unroll
                for (int i = 0; i < 8; i++) {
                    int k = k0 + i; float v = 0.f;
                    if (k < K) {
                        v = A0r[k];
                        if (A1r) v += A1r[k];
                        if (A2r) v += A2r[k];
                        if (j.kb) v += j.kb[k];
                    }
                    d[i] = v;
                }
            }
        }
        if (j.krelu) {
            #pragma unroll
            for (int i = 0; i < 16; i++) ra[i] = fmaxf(ra[i], 0.f);
        }
    };
    auto loadW = [&](int ti) {
        #pragma unroll
        for (int g = 0; g < WFT / 8; g++) {
            const int k0 = ti * 64 + wkg + g * 8;
            float* d = rw + g * 8;
            if (wvalid && k0 + 8 <= K) {
                ld8(d, Wbase + k0);
            } else {
                #pragma unroll
                for (int i = 0; i < 8; i++)
                    d[i] = (wvalid && (k0 + i) < K) ? Wbase[k0 + i] : 0.f;
            }
        }
    };

    loadA(t0);
    loadW(t0);

    for (int ti = t0; ti < t1; ti++) {
        __syncthreads();
        {
            uint4* p = (uint4*)&As[am][akg >> 1];
            p[0] = make_uint4(packh2(ra[0], ra[1]), packh2(ra[2], ra[3]),
                              packh2(ra[4], ra[5]), packh2(ra[6], ra[7]));
            p[1] = make_uint4(packh2(ra[8], ra[9]), packh2(ra[10], ra[11]),
                              packh2(ra[12], ra[13]), packh2(ra[14], ra[15]));
        }
        #pragma unroll
        for (int g = 0; g < WFT / 8; g++) {
            const float* r = rw + g * 8;
            *(uint4*)&Ws[wn][(wkg >> 1) + g * 4] =
                make_uint4(packh2(r[0], r[1]), packh2(r[2], r[3]),
                           packh2(r[4], r[5]), packh2(r[6], r[7]));
        }
        __syncthreads();

        if (ti + 1 < t1) { loadA(ti + 1); loadW(ti + 1); }

        uint32_t b[NF][8];
        #pragma unroll
        for (int nf = 0; nf < NF; nf++) {
            ldsm4p(&b[nf][0], bAddr[nf][0]);
            ldsm4p(&b[nf][4], bAddr[nf][1]);
        }
        #pragma unroll
        for (int ks = 0; ks < 4; ks++) {
            uint32_t a[2][4];
            ldsm4(a[0], aAddr[0][ks]);
            ldsm4(a[1], aAddr[1][ks]);
            #pragma unroll
            for (int nf = 0; nf < NF; nf++) {
                mma_f16(acc[0][nf], a[0], b[nf][2 * ks], b[nf][2 * ks + 1]);
                mma_f16(acc[1][nf], a[1], b[nf][2 * ks], b[nf][2 * ks + 1]);
            }
        }
    }
}

template<int BN>
__global__ __launch_bounds__(256) void sk_gemm_kernel(SKJob2 jobs)
{
    constexpr int NF = BN / 32;
    __shared__ __align__(16) uint32_t As[64][SPADH];
    __shared__ __align__(16) uint32_t Ws[BN][SPADH];

    const SKJob j = jobs.j[blockIdx.y];
    const int nb = blockIdx.x * BN;
    if (nb >= j.N) return;

    const int tiles = (j.K + 63) >> 6;
    const int KS = gridDim.z, kz = blockIdx.z;
    const int tpk = (tiles + KS - 1) / KS;
    const int t0 = kz * tpk;
    const int t1 = (t0 + tpk < tiles) ? (t0 + tpk) : tiles;

    float acc[2][NF][4] = {};
    if (t0 < t1)
        seg64<BN>(j, nb, t0, t1, As, Ws, acc);

    float* C = j.Cpart + (size_t)kz * 64 * j.N;
    const int tid = threadIdx.x, lane = tid & 31, wid = tid >> 5;
    const int warpM = wid >> 2, warpN = wid & 3;
    const int g = lane >> 2, t = lane & 3;

    #pragma unroll
    for (int mf = 0; mf < 2; mf++) {
        const int row = warpM * 32 + mf * 16 + g;
        #pragma unroll
        for (int nf = 0; nf < NF; nf++) {
            const int col = nb + warpN * (BN / 4) + nf * 8 + 2 * t;
            if (col < j.N) {
                *(float2*)&C[(size_t)row * j.N + col]       = make_float2(acc[mf][nf][0], acc[mf][nf][1]);
                *(float2*)&C[(size_t)(row + 8) * j.N + col] = make_float2(acc[mf][nf][2], acc[mf][nf][3]);
            }
        }
    }
}

// qpart reduce: 3 partials + bias
__global__ __launch_bounds__(256) void sk_reduce3_kernel(
    const float* __restrict__ part, const float* __restrict__ bias,
    float* __restrict__ outp)
{
    int idx = blockIdx.x * 256 + threadIdx.x;
    if (idx >= B_ * D_) return;
    int n = idx % D_;
    float v = bias[n] + part[idx] + part[(size_t)B_ * D_ + idx] + part[2 * (size_t)B_ * D_ + idx];
    outp[idx] = v;
}

// logits reduce: 2 partials + bias -> out
__global__ __launch_bounds__(256) void logits_reduce_kernel(
    const float* __restrict__ part, const float* __restrict__ bias,
    float* __restrict__ outp)
{
    int idx = blockIdx.x * 256 + threadIdx.x;
    if (idx >= B_ * V_) return;
    int n = idx % V_;
    outp[idx] = bias[n] + part[idx] + part[(size_t)B_ * V_ + idx];
}

// ---------------------------------------------------------------------------
// Fused attention scores (unchanged from R12): ktile=32, ping-pong smem.
// ---------------------------------------------------------------------------
#define SPH2 20
#define AS_WORDS (256 * SPH2)
#define WS_WORDS (128 * SPH2)
#define SC_DYN ((2 * AS_WORDS + 2 * WS_WORDS) * 4)   // 61440 B

__global__ __launch_bounds__(256, 1) void mma_scores_kernel(
    const __half* __restrict__ h16, const __half* __restrict__ w16,
    const float* __restrict__ qpart, const float* __restrict__ Wa2,
    float* __restrict__ spart)
{
    extern __shared__ uint32_t dyn[];
    uint32_t (*As)[256][SPH2] = (uint32_t(*)[256][SPH2])dyn;
    uint32_t (*Ws)[128][SPH2] = (uint32_t(*)[128][SPH2])(dyn + 2 * AS_WORDS);

    const int tid = threadIdx.x, lane = tid & 31, wid = tid >> 5;
    const int warpM = wid >> 1, warpN = wid & 1;
    const int g = lane >> 2, t = lane & 3;

    const __half* Abase = h16 + ((size_t)blockIdx.x * 256 + tid) * E_;
    const int wrow = tid & 127;
    const bool wldr = (tid < 128);

    const uint32_t ASO = AS_WORDS * 4, WSO = WS_WORDS * 4;
    uint32_t aA[4], bA[8];
    #pragma unroll
    for (int mf = 0; mf < 4; mf++)
        aA[mf] = (uint32_t)__cvta_generic_to_shared(
            &As[0][warpM * 64 + mf * 16 + (lane & 15)][4 * (lane >> 4)]);
    #pragma unroll
    for (int nf = 0; nf < 8; nf++)
        bA[nf] = (uint32_t)__cvta_generic_to_shared(
            &Ws[0][warpN * 64 + nf * 8 + (lane & 7)][4 * ((lane >> 3) & 1)]);

    float sacc[4][2] = {};

    const int tile0 = blockIdx.y * 5;
    for (int tile = tile0; tile < tile0 + 5; tile++) {
        const int nb = tile * 128;
        const bool wv = wldr && (nb + wrow) < D_;
        const __half* Wbase = w16 + (size_t)(nb + wrow) * E_;

        uint4 ra[4], rw[4];
        float acc[4][8][4] = {};

        auto loadA = [&](int ti) {
            const uint4* p = (const uint4*)(Abase + ti * 32);
            ra[0] = p[0]; ra[1] = p[1]; ra[2] = p[2]; ra[3] = p[3];
        };
        auto loadW = [&](int ti) {
            if (wv) {
                const uint4* p = (const uint4*)(Wbase + ti * 32);
                rw[0] = p[0]; rw[1] = p[1]; rw[2] = p[2]; rw[3] = p[3];
            } else if (wldr) {
                rw[0] = rw[1] = rw[2] = rw[3] = make_uint4(0, 0, 0, 0);
            }
        };
        auto stsAB = [&](int buf) {
            uint4* pa = (uint4*)&As[buf][tid][0];
            pa[0] = ra[0]; pa[1] = ra[1]; pa[2] = ra[2]; pa[3] = ra[3];
            if (wldr) {
                uint4* pw = (uint4*)&Ws[buf][wrow][0];
                pw[0] = rw[0]; pw[1] = rw[1]; pw[2] = rw[2]; pw[3] = rw[3];
            }
        };
        auto domma = [&](int buf) {
            const uint32_t ao = buf * ASO, wo = buf * WSO;
            #pragma unroll
            for (int ks = 0; ks < 2; ks++) {
                uint32_t b[8][2];
                #pragma unroll
                for (int nf = 0; nf < 8; nf++) ldsm2(b[nf], bA[nf] + wo + ks * 32);
                #pragma unroll
                for (int mf = 0; mf < 4; mf++) {
                    uint32_t a[4];
                    ldsm4(a, aA[mf] + ao + ks * 32);
                    #pragma unroll
                    for (int nf = 0; nf < 8; nf++)
                        mma_f16(acc[mf][nf], a, b[nf][0], b[nf][1]);
                }
            }
        };

        loadA(0); loadW(0);
        __syncthreads();
        stsAB(0);
        loadA(1); loadW(1);

        for (int ti = 0; ti < E_ / 32; ti++) {
            __syncthreads();
            if (ti + 1 < E_ / 32) stsAB((ti + 1) & 1);
            if (ti + 2 < E_ / 32) { loadA(ti + 2); loadW(ti + 2); }
            domma(ti & 1);
        }

        #pragma unroll
        for (int mf = 0; mf < 4; mf++) {
            const int r0 = warpM * 64 + mf * 16 + g;
            const int b0 = r0 & 63, b1 = (r0 + 8) & 63;
            #pragma unroll
            for (int nf = 0; nf < 8; nf++) {
                const int col = nb + warpN * 64 + nf * 8 + 2 * t;
                if (col < D_) {
                    float2 w  = *(const float2*)(Wa2 + col);
                    float2 q0 = *(const float2*)(qpart + (size_t)b0 * D_ + col);
                    float2 q1 = *(const float2*)(qpart + (size_t)b1 * D_ + col);
                    sacc[mf][0] += fmaxf(acc[mf][nf][0] + q0.x, 0.f) * w.x
                                 + fmaxf(acc[mf][nf][1] + q0.y, 0.f) * w.y;
                    sacc[mf][1] += fmaxf(acc[mf][nf][2] + q1.x, 0.f) * w.x
                                 + fmaxf(acc[mf][nf][3] + q1.y, 0.f) * w.y;
                }
            }
        }
    }

    __syncthreads();
    float* red = (float*)dyn;
    #pragma unroll
    for (int mf = 0; mf < 4; mf++) {
        const int r0 = warpM * 64 + mf * 16 + g;
        red[r0 * 9 + warpN * 4 + t]       = sacc[mf][0];
        red[(r0 + 8) * 9 + warpN * 4 + t] = sacc[mf][1];
    }
    __syncthreads();
    {
        const int row = tid;
        float a = 0.f;
        #pragma unroll
        for (int c = 0; c < 8; c++) a += red[row * 9 + c];
        const int s = blockIdx.x * 4 + (row >> 6);
        const int b = row & 63;
        spart[(size_t)blockIdx.y * S_ * B_ + (size_t)s * B_ + b] = a;
    }
}

// ---------------------------------------------------------------------------
// Small kernels
// ---------------------------------------------------------------------------
__global__ void havg_kernel(const float* __restrict__ h, float* __restrict__ havg)
{
    int b = blockIdx.x;
    int e = blockIdx.y * 256 + threadIdx.x;
    float s = 0.f;
    for (int si = 0; si < S_; si++)
        s += h[((size_t)si * B_ + b) * E_ + e];
    havg[(size_t)b * E_ + e] = s * (1.f / (float)S_);
}

__global__ __launch_bounds__(256) void softmax_beta_kernel(
    const float* __restrict__ spart,
    const float* __restrict__ hp0, const float* __restrict__ hp1,
    const float* __restrict__ hp2, const float* __restrict__ bh2,
    const float* __restrict__ Wb, const float* __restrict__ bb,
    const float* __restrict__ ba2,
    float* __restrict__ aw_out, float* __restrict__ beta)
{
    int b = blockIdx.x, tid = threadIdx.x;
    __shared__ float sm[256];

    float p = 0.f;
    for (int d = tid; d < D_; d += 256) {
        size_t i = (size_t)b * D_ + d;
        float hv = hp0[i] + hp1[i] + hp2[i] + bh2[d];
        p = fmaf(hv, Wb[d], p);
    }
    sm[tid] = p; __syncthreads();
    for (int o = 128; o > 0; o >>= 1) { if (tid < o) sm[tid] += sm[tid + o]; __syncthreads(); }
    if (tid == 0) beta[b] = 1.f / (1.f + expf(-(sm[0] + bb[0])));
    __syncthreads();

    float v = -3.4e38f;
    if (tid < S_) {
        size_t idx = (size_t)tid * B_ + b;
        v = spart[idx] + spart[(size_t)S_ * B_ + idx] + spart[2 * (size_t)S_ * B_ + idx] + ba2[0];
    }
    sm[tid] = v; __syncthreads();
    for (int o = 128; o > 0; o >>= 1) { if (tid < o) sm[tid] = fmaxf(sm[tid], sm[tid + o]); __syncthreads(); }
    float mx = sm[0]; __syncthreads();
    float e = (tid < S_) ? expf(v - mx) : 0.f;
    sm[tid] = e; __syncthreads();
    for (int o = 128; o > 0; o >>= 1) { if (tid < o) sm[tid] += sm[tid + o]; __syncthreads(); }
    float inv = 1.f / sm[0];
    if (tid < S_) aw_out[(size_t)tid * B_ + b] = e * inv;
}

__global__ void ctx_kernel(const float* __restrict__ h, const float* __restrict__ aw,
                           const float* __restrict__ beta, float* __restrict__ ctx)
{
    int b = blockIdx.x;
    int e = blockIdx.y * 256 + threadIdx.x;
    float s = 0.f;
    for (int si = 0; si < S_; si++)
        s = fmaf(aw[(size_t)si * B_ + b], h[((size_t)si * B_ + b) * E_ + e], s);
    ctx[(size_t)b * E_ + e] = s * beta[b];
}

__global__ __launch_bounds__(256) void argmax_kernel(const float* __restrict__ y, int* __restrict__ amax)
{
    int b = blockIdx.x, tid = threadIdx.x;
    float bm = -3.4e38f; int bi = 0;
    for (int i = tid; i < V_; i += 256) {
        float v = y[(size_t)b * V_ + i];
        if (v > bm) { bm = v; bi = i; }
    }
    __shared__ float sv[256];
    __shared__ int si_[256];
    sv[tid] = bm; si_[tid] = bi; __syncthreads();
    for (int o = 128; o > 0; o >>= 1) {
        if (tid < o) {
            if (sv[tid + o] > sv[tid] || (sv[tid + o] == sv[tid] && si_[tid + o] < si_[tid])) {
                sv[tid] = sv[tid + o]; si_[tid] = si_[tid + o];
            }
        }
        __syncthreads();
    }
    if (tid == 0) amax[b] = si_[0];
}

__global__ void xbuild_kernel(const float* __restrict__ emb, const int* __restrict__ Etm1,
                              const float* __restrict__ ctx, float* __restrict__ x)
{
    int b = blockIdx.x;
    int i = blockIdx.y * 256 + threadIdx.x;
    if (i < W_) x[(size_t)b * WE_ + i] = emb[(size_t)Etm1[b] * W_ + i];
    else        x[(size_t)b * WE_ + i] = ctx[(size_t)b * E_ + (i - W_)];
}

// LSTM pointwise; sums 4 gate partials + biases, c0 from 3 partials + bias.
__global__ void lstm_kernel(const float* __restrict__ gp0, const float* __restrict__ gp1,
                            const float* __restrict__ b_ih, const float* __restrict__ b_hh,
                            const float* __restrict__ cp0, const float* __restrict__ cp1,
                            const float* __restrict__ cp2, const float* __restrict__ bc2,
                            float* __restrict__ out, float* __restrict__ z)
{
    const size_t P4 = (size_t)B_ * 4 * D_;
    int b = blockIdx.x;
    int d = blockIdx.y * 256 + threadIdx.x;
    if (d >= D_) return;
    const size_t base = (size_t)b * 4 * D_;
    float gi = gp0[base + d]        + gp0[P4 + base + d]        + gp1[base + d]        + gp1[P4 + base + d]        + b_ih[d]        + b_hh[d];
    float gf = gp0[base + D_ + d]   + gp0[P4 + base + D_ + d]   + gp1[base + D_ + d]   + gp1[P4 + base + D_ + d]   + b_ih[D_ + d]   + b_hh[D_ + d];
    float gg = gp0[base + 2*D_ + d] + gp0[P4 + base + 2*D_ + d] + gp1[base + 2*D_ + d] + gp1[P4 + base + 2*D_ + d] + b_ih[2*D_ + d] + b_hh[2*D_ + d];
    float go = gp0[base + 3*D_ + d] + gp0[P4 + base + 3*D_ + d] + gp1[base + 3*D_ + d] + gp1[P4 + base + 3*D_ + d] + b_ih[3*D_ + d] + b_hh[3*D_ + d];
    size_t ci = (size_t)b * D_ + d;
    float c0 = cp0[ci] + cp1[ci] + cp2[ci] + bc2[d];
    float ig = 1.f / (1.f + expf(-gi));
    float fg = 1.f / (1.f + expf(-gf));
    float gt = tanhf(gg);
    float og = 1.f / (1.f + expf(-go));
    float c = fmaf(fg, c0, ig * gt);
    float ht = og * tanhf(c);
    out[(size_t)B_ * V_ + (size_t)b * D_ + d] = ht;
    out[(size_t)B_ * V_ + (size_t)B_ * D_ + (size_t)b * D_ + d] = c;
    z[(size_t)b * DWE_ + d] = ht;
}

__global__ void zbuild_kernel(const float* __restrict__ emb, const int* __restrict__ amax,
                              const float* __restrict__ ctx, float* __restrict__ z)
{
    int b = blockIdx.x;
    int i = blockIdx.y * 256 + threadIdx.x;
    if (i < W_) z[(size_t)b * DWE_ + D_ + i] = emb[(size_t)amax[b] * W_ + i];
    else        z[(size_t)b * DWE_ + D_ + i] = ctx[(size_t)b * E_ + (i - W_)];
}

// ---------------------------------------------------------------------------
// Launch
// ---------------------------------------------------------------------------
extern "C" void kernel_launch(void* const* d_in, const int* in_sizes, int n_in,
                              void* d_out, int out_size)
{
    const int*   E_tm1 = (const int*)d_in[0];
    const float* y_tm1 = (const float*)d_in[1];
    const float* h     = (const float*)d_in[2];
    const float* emb   = (const float*)d_in[3];
    const float* W_ih  = (const float*)d_in[4];
    const float* b_ih  = (const float*)d_in[5];
    const float* W_hh  = (const float*)d_in[6];
    const float* b_hh  = (const float*)d_in[7];
    const float* W_out = (const float*)d_in[8];
    const float* b_out = (const float*)d_in[9];
    const float* Wh1 = (const float*)d_in[10]; const float* bh1 = (const float*)d_in[11];
    const float* Wh2 = (const float*)d_in[12]; const float* bh2 = (const float*)d_in[13];
    const float* Wc1 = (const float*)d_in[14]; const float* bc1 = (const float*)d_in[15];
    const float* Wc2 = (const float*)d_in[16]; const float* bc2 = (const float*)d_in[17];
    const float* Wa1 = (const float*)d_in[18]; const float* ba1 = (const float*)d_in[19];
    const float* Wa2 = (const float*)d_in[20]; const float* ba2 = (const float*)d_in[21];
    const float* Wb  = (const float*)d_in[22]; const float* bb  = (const float*)d_in[23];
    float* out = (float*)d_out;

    Scratch* s = nullptr;
    cudaGetSymbolAddress((void**)&s, g_s);

    cudaFuncSetAttribute(mma_scores_kernel,
                         cudaFuncAttributeMaxDynamicSharedMemorySize, SC_DYN);

    const int GN_D  = (D_ + 63) / 64;            // 29
    const int GN_4D = (4 * D_ + 127) / 128;      // 57
    const int GN_V  = V_ / 128;                  // 250
    const int CONV_BLK = (S_ * B_ * E_ / 8 + D_ * E_ / 8 + 255) / 256;

    // 0. fp16 preconversion of h and Wa1 key-slice
    conv16_kernel<<<CONV_BLK, 256>>>(h, Wa1, s->h16, s->w16);

    // 1. encoder mean
    havg_kernel<<<dim3(B_, E_ / 256), 256>>>(h, s->havg);

    // 2. init-state layer1 -> partials (KS=3)
    {
        SKJob2 jj;
        jj.j[0] = {s->havg, nullptr, nullptr, nullptr, 0, Wh1, E_, E_, D_, s->skpA[0][0]};
        jj.j[1] = {s->havg, nullptr, nullptr, nullptr, 0, Wc1, E_, E_, D_, s->skpA[1][0]};
        sk_gemm_kernel<64><<<dim3(GN_D, 2, 3), 256>>>(jj);
    }
    // 3. layer2, A = relu(sum of 3 L1 partials + b1) fused (KS=3)
    {
        SKJob2 jj;
        jj.j[0] = {s->skpA[0][0], s->skpA[0][1], s->skpA[0][2], bh1, 1, Wh2, D_, D_, D_, s->skpB[0][0]};
        jj.j[1] = {s->skpA[1][0], s->skpA[1][1], s->skpA[1][2], bc1, 1, Wc2, D_, D_, D_, s->skpB[1][0]};
        sk_gemm_kernel<64><<<dim3(GN_D, 2, 3), 256>>>(jj);
    }
    // 4. qpart partials = (h0 = sum L2 partials + bh2) @ Wa1[:, :D]^T  (KS=3)
    {
        SKJob2 jj;
        jj.j[0] = {s->skpB[0][0], s->skpB[0][1], s->skpB[0][2], bh2, 0, Wa1, D_, DE_, D_, s->skpA[0][0]};
        jj.j[1] = jj.j[0];
        sk_gemm_kernel<64><<<dim3(GN_D, 1, 3), 256>>>(jj);
    }
    // 5. qpart reduce (+ ba1)
    sk_reduce3_kernel<<<(B_ * D_ + 255) / 256, 256>>>(s->skpA[0][0], ba1, s->qpart);

    // 6. fused scores GEMM
    mma_scores_kernel<<<dim3(S_ / 4, 3), 256, SC_DYN>>>(
        s->h16, s->w16, s->qpart, Wa2, s->spart);

    // 7. argmax of y_tm1
    argmax_kernel<<<B_, 256>>>(y_tm1, s->amax);

    // 8. softmax + beta (h0 virtual from partials)
    float* aw_out = out + (size_t)B_ * V_ + 2 * (size_t)B_ * D_;
    softmax_beta_kernel<<<B_, 256>>>(s->spart, s->skpB[0][0], s->skpB[0][1], s->skpB[0][2],
                                     bh2, Wb, bb, ba2, aw_out, s->beta);

    // 9. context
    ctx_kernel<<<dim3(B_, E_ / 256), 256>>>(h, aw_out, s->beta, s->ctx);

    // 10. LSTM input + gates (split-K 2 on both jobs)
    xbuild_kernel<<<dim3(B_, WE_ / 256), 256>>>(emb, E_tm1, s->ctx, s->x);
    {
        SKJob2 jj;
        jj.j[0] = {s->x, nullptr, nullptr, nullptr, 0, W_ih, WE_, WE_, 4 * D_, s->gp0[0]};
        jj.j[1] = {s->skpB[0][0], s->skpB[0][1], s->skpB[0][2], bh2, 0, W_hh, D_, D_, 4 * D_, s->gp1[0]};
        sk_gemm_kernel<128><<<dim3(GN_4D, 2, 2), 256>>>(jj);
    }

    // 11. LSTM pointwise (4 gate partials; c0 from partials)
    lstm_kernel<<<dim3(B_, (D_ + 255) / 256), 256>>>(
        s->gp0[0], s->gp1[0], b_ih, b_hh,
        s->skpB[1][0], s->skpB[1][1], s->skpB[1][2], bc2, out, s->z);

    // 12. z tail
    zbuild_kernel<<<dim3(B_, WE_ / 256), 256>>>(emb, s->amax, s->ctx, s->z);

    // 13. logits (split-K 2) + reduce
    {
        SKJob2 jj;
        jj.j[0] = {s->z, nullptr, nullptr, nullptr, 0, W_out, DWE_, DWE_, V_, s->lgp[0]};
        jj.j[1] = jj.j[0];
        sk_gemm_kernel<128><<<dim3(GN_V, 1, 2), 256>>>(jj);
    }
    logits_reduce_kernel<<<(B_ * V_ + 255) / 256, 256>>>(s->lgp[0], b_out, out);
}

// round 16
// speedup vs baseline: 1.2649x; 1.1405x over previous
#include <cuda_runtime.h>
#include <cuda_fp16.h>
#include <math.h>
#include <stdint.h>

#define S_ 196
#define B_ 64
#define E_ 1024
#define D_ 1800
#define W_ 512
#define V_ 32000
#define WE_ (W_ + E_)       // 1536
#define DE_ (D_ + E_)       // 2824
#define DWE_ (D_ + W_ + E_) // 3336

// ---------------------------------------------------------------------------
// Scratch
// ---------------------------------------------------------------------------
struct Scratch {
    float havg[B_ * E_];
    float skpA[2][3][B_ * D_];
    float skpB[2][3][B_ * D_];
    float qpart[B_ * D_];
    float spart[3 * S_ * B_];
    float beta[B_];
    float ctx[B_ * E_];
    float x[B_ * WE_];
    float z[B_ * DWE_];
    float gp0[2][B_ * 4 * D_];
    float gp1[2][B_ * 4 * D_];
    float lgp[2][B_ * V_];
    int   amax[B_];
    __half h16[S_ * B_ * E_];   // fp16 copy of h
    __half w16[D_ * E_];        // fp16 copy of Wa1[:, D:]
};
__device__ Scratch g_s;

// ---------------------------------------------------------------------------
// fp16 MMA helpers
// ---------------------------------------------------------------------------
__device__ __forceinline__ uint32_t packh2(float a, float b) {
    __half2 h = __floats2half2_rn(a, b);
    return *(uint32_t*)&h;
}
__device__ __forceinline__ void mma_f16(float (&c)[4], const uint32_t (&a)[4],
                                        const uint32_t b0, const uint32_t b1) {
    asm volatile(
        "mma.sync.aligned.m16n8k16.row.col.f32.f16.f16.f32 "
        "{%0,%1,%2,%3},{%4,%5,%6,%7},{%8,%9},{%0,%1,%2,%3};"
        : "+f"(c[0]), "+f"(c[1]), "+f"(c[2]), "+f"(c[3])
        : "r"(a[0]), "r"(a[1]), "r"(a[2]), "r"(a[3]), "r"(b0), "r"(b1));
}
__device__ __forceinline__ void ldsm4(uint32_t (&r)[4], uint32_t addr) {
    asm volatile("ldmatrix.sync.aligned.m8n8.x4.shared.b16 {%0,%1,%2,%3}, [%4];"
        : "=r"(r[0]), "=r"(r[1]), "=r"(r[2]), "=r"(r[3]) : "r"(addr));
}
__device__ __forceinline__ void ldsm4p(uint32_t* r, uint32_t addr) {
    asm volatile("ldmatrix.sync.aligned.m8n8.x4.shared.b16 {%0,%1,%2,%3}, [%4];"
        : "=r"(r[0]), "=r"(r[1]), "=r"(r[2]), "=r"(r[3]) : "r"(addr));
}
__device__ __forceinline__ void ldsm2(uint32_t (&r)[2], uint32_t addr) {
    asm volatile("ldmatrix.sync.aligned.m8n8.x2.shared.b16 {%0,%1}, [%2];"
        : "=r"(r[0]), "=r"(r[1]) : "r"(addr));
}
__device__ __forceinline__ void ld8(float* d, const float* p) {
    float4 a = ((const float4*)p)[0], b = ((const float4*)p)[1];
    d[0]=a.x; d[1]=a.y; d[2]=a.z; d[3]=a.w; d[4]=b.x; d[5]=b.y; d[6]=b.z; d[7]=b.w;
}
__device__ __forceinline__ void add8(float* d, const float* p) {
    float4 a = ((const float4*)p)[0], b = ((const float4*)p)[1];
    d[0]+=a.x; d[1]+=a.y; d[2]+=a.z; d[3]+=a.w; d[4]+=b.x; d[5]+=b.y; d[6]+=b.z; d[7]+=b.w;
}
__device__ __forceinline__ void cpa16(uint32_t dst, const void* src, int sz) {
    asm volatile("cp.async.cg.shared.global [%0], [%1], 16, %2;"
        :: "r"(dst), "l"(src), "r"(sz) : "memory");
}
#define CPA_COMMIT() asm volatile("cp.async.commit_group;" ::: "memory")
#define CPA_WAIT2()  asm volatile("cp.async.wait_group 2;" ::: "memory")

// ktile=64 chain layout: row stride 36 words; bases 4r mod 32 conflict-free.
#define SPADH 36

// ---------------------------------------------------------------------------
// fp32 -> fp16 preconversion: h16 = h, w16 = Wa1[:, D:] (row stride E)
// ---------------------------------------------------------------------------
__global__ __launch_bounds__(256) void conv16_kernel(
    const float* __restrict__ h, const float* __restrict__ Wa1,
    __half* __restrict__ h16, __half* __restrict__ w16)
{
    const int HT = S_ * B_ * E_ / 8;
    const int WT = D_ * E_ / 8;
    int idx = blockIdx.x * 256 + threadIdx.x;
    if (idx < HT) {
        const float4* p = (const float4*)(h + (size_t)idx * 8);
        float4 a = p[0], b = p[1];
        *(uint4*)(h16 + (size_t)idx * 8) =
            make_uint4(packh2(a.x, a.y), packh2(a.z, a.w),
                       packh2(b.x, b.y), packh2(b.z, b.w));
    } else if (idx - HT < WT) {
        int j = idx - HT;
        int n = j / (E_ / 8), k8 = j % (E_ / 8);
        const float4* p = (const float4*)(Wa1 + (size_t)n * DE_ + D_ + k8 * 8);
        float4 a = p[0], b = p[1];
        *(uint4*)(w16 + (size_t)n * E_ + k8 * 8) =
            make_uint4(packh2(a.x, a.y), packh2(a.z, a.w),
                       packh2(b.x, b.y), packh2(b.z, b.w));
    }
}

// ---------------------------------------------------------------------------
// Small-GEMM K-segment, fp16 MMA, ktile=64, fused A-side reduce (from R13)
// ---------------------------------------------------------------------------
struct SKJob {
    const float* A0; const float* A1p; const float* A2p;
    const float* kb; int krelu;
    const float* W; int K; int ldw; int N; float* Cpart;
};
struct SKJob2 { SKJob j[2]; };

template<int BN>
__device__ __forceinline__ void seg64(
    const SKJob& j, const int nb, const int t0, const int t1,
    uint32_t As[64][SPADH], uint32_t Ws[BN][SPADH],
    float (&acc)[2][BN / 32][4])
{
    constexpr int NF  = BN / 32;
    constexpr int WFT = (BN == 64) ? 16 : 32;
    const int tid  = threadIdx.x;
    const int lane = tid & 31, wid = tid >> 5;
    const int warpM = wid >> 2, warpN = wid & 3;

    const int am  = tid & 63, akg = (tid >> 6) * 16;
    const int wn  = (BN == 64) ? (tid & 63) : (tid & 127);
    const int wkg = (BN == 64) ? ((tid >> 6) * 16) : ((tid >> 7) * 32);
    const bool wvalid = (nb + wn) < j.N;
    const int K = j.K;
    const float* A0r = j.A0 + (size_t)am * K;
    const float* A1r = j.A1p ? j.A1p + (size_t)am * K : nullptr;
    const float* A2r = j.A2p ? j.A2p + (size_t)am * K : nullptr;
    const float* Wbase = j.W + (size_t)(nb + wn) * j.ldw;

    uint32_t aAddr[2][4], bAddr[NF][2];
    #pragma unroll
    for (int mf = 0; mf < 2; mf++)
        #pragma unroll
        for (int ks = 0; ks < 4; ks++)
            aAddr[mf][ks] = (uint32_t)__cvta_generic_to_shared(
                &As[warpM * 32 + mf * 16 + (lane & 15)][ks * 8 + 4 * (lane >> 4)]);
    #pragma unroll
    for (int nf = 0; nf < NF; nf++)
        #pragma unroll
        for (int hh = 0; hh < 2; hh++)
            bAddr[nf][hh] = (uint32_t)__cvta_generic_to_shared(
                &Ws[warpN * (BN / 4) + nf * 8 + (lane & 7)][hh * 16 + 4 * (lane >> 3)]);

    float ra[16], rw[WFT];

    auto loadA = [&](int ti) {
        #pragma unroll
        for (int g = 0; g < 2; g++) {
            const int k0 = ti * 64 + akg + g * 8;
            float* d = ra + g * 8;
            if (k0 + 8 <= K) {
                ld8(d, A0r + k0);
                if (A1r) add8(d, A1r + k0);
                if (A2r) add8(d, A2r + k0);
                if (j.kb) add8(d, j.kb + k0);
            } else {
                #pragma unroll
                for (int i = 0; i < 8; i++) {
                    int k = k0 + i; float v = 0.f;
                    if (k < K) {
                        v = A0r[k];
                        if (A1r) v += A1r[k];
                        if (A2r) v += A2r[k];
                        if (j.kb) v += j.kb[k];
                    }
                    d[i] = v;
                }
            }
        }
        if (j.krelu) {
            #pragma unroll
            for (int i = 0; i < 16; i++) ra[i] = fmaxf(ra[i], 0.f);
        }
    };
    auto loadW = [&](int ti) {
        #pragma unroll
        for (int g = 0; g < WFT / 8; g++) {
            const int k0 = ti * 64 + wkg + g * 8;
            float* d = rw + g * 8;
            if (wvalid && k0 + 8 <= K) {
                ld8(d, Wbase + k0);
            } else {
                #pragma unroll
                for (int i = 0; i < 8; i++)
                    d[i] = (wvalid && (k0 + i) < K) ? Wbase[k0 + i] : 0.f;
            }
        }
    };

    loadA(t0);
    loadW(t0);

    for (int ti = t0; ti < t1; ti++) {
        __syncthreads();
        {
            uint4* p = (uint4*)&As[am][akg >> 1];
            p[0] = make_uint4(packh2(ra[0], ra[1]), packh2(ra[2], ra[3]),
                              packh2(ra[4], ra[5]), packh2(ra[6], ra[7]));
            p[1] = make_uint4(packh2(ra[8], ra[9]), packh2(ra[10], ra[11]),
                              packh2(ra[12], ra[13]), packh2(ra[14], ra[15]));
        }
        #pragma unroll
        for (int g = 0; g < WFT / 8; g++) {
            const float* r = rw + g * 8;
            *(uint4*)&Ws[wn][(wkg >> 1) + g * 4] =
                make_uint4(packh2(r[0], r[1]), packh2(r[2], r[3]),
                           packh2(r[4], r[5]), packh2(r[6], r[7]));
        }
        __syncthreads();

        if (ti + 1 < t1) { loadA(ti + 1); loadW(ti + 1); }

        uint32_t b[NF][8];
        #pragma unroll
        for (int nf = 0; nf < NF; nf++) {
            ldsm4p(&b[nf][0], bAddr[nf][0]);
            ldsm4p(&b[nf][4], bAddr[nf][1]);
        }
        #pragma unroll
        for (int ks = 0; ks < 4; ks++) {
            uint32_t a[2][4];
            ldsm4(a[0], aAddr[0][ks]);
            ldsm4(a[1], aAddr[1][ks]);
            #pragma unroll
            for (int nf = 0; nf < NF; nf++) {
                mma_f16(acc[0][nf], a[0], b[nf][2 * ks], b[nf][2 * ks + 1]);
                mma_f16(acc[1][nf], a[1], b[nf][2 * ks], b[nf][2 * ks + 1]);
            }
        }
    }
}

template<int BN>
__global__ __launch_bounds__(256) void sk_gemm_kernel(SKJob2 jobs)
{
    constexpr int NF = BN / 32;
    __shared__ __align__(16) uint32_t As[64][SPADH];
    __shared__ __align__(16) uint32_t Ws[BN][SPADH];

    const SKJob j = jobs.j[blockIdx.y];
    const int nb = blockIdx.x * BN;
    if (nb >= j.N) return;

    const int tiles = (j.K + 63) >> 6;
    const int KS = gridDim.z, kz = blockIdx.z;
    const int tpk = (tiles + KS - 1) / KS;
    const int t0 = kz * tpk;
    const int t1 = (t0 + tpk < tiles) ? (t0 + tpk) : tiles;

    float acc[2][NF][4] = {};
    if (t0 < t1)
        seg64<BN>(j, nb, t0, t1, As, Ws, acc);

    float* C = j.Cpart + (size_t)kz * 64 * j.N;
    const int tid = threadIdx.x, lane = tid & 31, wid = tid >> 5;
    const int warpM = wid >> 2, warpN = wid & 3;
    const int g = lane >> 2, t = lane & 3;

    #pragma unroll
    for (int mf = 0; mf < 2; mf++) {
        const int row = warpM * 32 + mf * 16 + g;
        #pragma unroll
        for (int nf = 0; nf < NF; nf++) {
            const int col = nb + warpN * (BN / 4) + nf * 8 + 2 * t;
            if (col < j.N) {
                *(float2*)&C[(size_t)row * j.N + col]       = make_float2(acc[mf][nf][0], acc[mf][nf][1]);
                *(float2*)&C[(size_t)(row + 8) * j.N + col] = make_float2(acc[mf][nf][2], acc[mf][nf][3]);
            }
        }
    }
}

__global__ __launch_bounds__(256) void sk_reduce3_kernel(
    const float* __restrict__ part, const float* __restrict__ bias,
    float* __restrict__ outp)
{
    int idx = blockIdx.x * 256 + threadIdx.x;
    if (idx >= B_ * D_) return;
    int n = idx % D_;
    float v = bias[n] + part[idx] + part[(size_t)B_ * D_ + idx] + part[2 * (size_t)B_ * D_ + idx];
    outp[idx] = v;
}

__global__ __launch_bounds__(256) void logits_reduce_kernel(
    const float* __restrict__ part, const float* __restrict__ bias,
    float* __restrict__ outp)
{
    int idx = blockIdx.x * 256 + threadIdx.x;
    if (idx >= B_ * V_) return;
    int n = idx % V_;
    outp[idx] = bias[n] + part[idx] + part[(size_t)B_ * V_ + idx];
}

// ---------------------------------------------------------------------------
// Fused attention scores v3: cp.async 4-stage pipeline, BM=128, BN=128,
// 8 warps (4M x 2N, warp tile 32x64), 2 blocks/SM. grid = (98, 3).
// ---------------------------------------------------------------------------
#define SCS 20                      // row stride in words; bases 20r mod 32 CF
#define A_STW (128 * SCS)           // 2560 words per stage
#define W_STW (128 * SCS)
#define NSTG 4
#define SC_DYN ((NSTG * (A_STW + W_STW)) * 4)   // 81920 B

__global__ __launch_bounds__(256, 2) void mma_scores_kernel(
    const __half* __restrict__ h16, const __half* __restrict__ w16,
    const float* __restrict__ qpart, const float* __restrict__ Wa2,
    float* __restrict__ spart)
{
    extern __shared__ __align__(16) uint32_t dyn[];
    uint32_t* Asm = dyn;                    // A stages
    uint32_t* Wsm = dyn + NSTG * A_STW;     // W stages

    const int tid = threadIdx.x, lane = tid & 31, wid = tid >> 5;
    const int warpM = wid >> 1, warpN = wid & 1;
    const int gq = lane >> 2, t = lane & 3;

    // loader: 2 threads per row, 32 bytes (2 x cp.async.16) each
    const int lrow = tid >> 1;
    const int lh   = tid & 1;
    const __half* Ag = h16 + ((size_t)blockIdx.x * 128 + lrow) * E_ + lh * 16;
    const int tile0 = blockIdx.y * 5;

    const uint32_t aDst = (uint32_t)__cvta_generic_to_shared(&Asm[lrow * SCS + lh * 8]);
    const uint32_t wDst = (uint32_t)__cvta_generic_to_shared(&Wsm[lrow * SCS + lh * 8]);

    uint32_t aA[2], bA[8];
    #pragma unroll
    for (int mf = 0; mf < 2; mf++)
        aA[mf] = (uint32_t)__cvta_generic_to_shared(
            &Asm[(warpM * 32 + mf * 16 + (lane & 15)) * SCS + 4 * (lane >> 4)]);
    #pragma unroll
    for (int nf = 0; nf < 8; nf++)
        bA[nf] = (uint32_t)__cvta_generic_to_shared(
            &Wsm[(warpN * 64 + nf * 8 + (lane & 7)) * SCS + 4 * ((lane >> 3) & 1)]);

    auto issue = [&](int st) {
        const int tile = st >> 5, kk = st & 31;
        const int slot = st & 3;
        const __half* asrc = Ag + kk * 32;
        const uint32_t ad = aDst + (uint32_t)slot * (A_STW * 4);
        cpa16(ad,      asrc,     16);
        cpa16(ad + 16, asrc + 8, 16);
        const int wr = (tile0 + tile) * 128 + lrow;
        const bool wv = wr < D_;
        const __half* wsrc = wv ? (w16 + (size_t)wr * E_ + kk * 32 + lh * 16) : w16;
        const int sz = wv ? 16 : 0;
        const uint32_t wd = wDst + (uint32_t)slot * (W_STW * 4);
        cpa16(wd,      wsrc,     sz);
        cpa16(wd + 16, wsrc + 8, sz);
    };

    float sacc[2][2] = {};
    float acc[2][8][4] = {};

    issue(0); CPA_COMMIT();
    issue(1); CPA_COMMIT();
    issue(2); CPA_COMMIT();

    for (int it = 0; it < 160; it++) {
        CPA_WAIT2();
        __syncthreads();
        if (it + 3 < 160) issue(it + 3);
        CPA_COMMIT();

        const uint32_t ao = (uint32_t)(it & 3) * (A_STW * 4);
        const uint32_t wo = (uint32_t)(it & 3) * (W_STW * 4);
        #pragma unroll
        for (int ks = 0; ks < 2; ks++) {
            uint32_t b[8][2];
            #pragma unroll
            for (int nf = 0; nf < 8; nf++) ldsm2(b[nf], bA[nf] + wo + ks * 32);
            #pragma unroll
            for (int mf = 0; mf < 2; mf++) {
                uint32_t a[4];
                ldsm4(a, aA[mf] + ao + ks * 32);
                #pragma unroll
                for (int nf = 0; nf < 8; nf++)
                    mma_f16(acc[mf][nf], a, b[nf][0], b[nf][1]);
            }
        }

        if ((it & 31) == 31) {
            const int nb = (tile0 + (it >> 5)) * 128;
            #pragma unroll
            for (int mf = 0; mf < 2; mf++) {
                const int r0 = warpM * 32 + mf * 16 + gq;
                const int b0 = r0 & 63, b1 = (r0 + 8) & 63;
                #pragma unroll
                for (int nf = 0; nf < 8; nf++) {
                    const int col = nb + warpN * 64 + nf * 8 + 2 * t;
                    if (col < D_) {
                        float2 w  = *(const float2*)(Wa2 + col);
                        float2 q0 = *(const float2*)(qpart + (size_t)b0 * D_ + col);
                        float2 q1 = *(const float2*)(qpart + (size_t)b1 * D_ + col);
                        sacc[mf][0] += fmaxf(acc[mf][nf][0] + q0.x, 0.f) * w.x
                                     + fmaxf(acc[mf][nf][1] + q0.y, 0.f) * w.y;
                        sacc[mf][1] += fmaxf(acc[mf][nf][2] + q1.x, 0.f) * w.x
                                     + fmaxf(acc[mf][nf][3] + q1.y, 0.f) * w.y;
                    }
                    #pragma unroll
                    for (int i = 0; i < 4; i++) acc[mf][nf][i] = 0.f;
                }
            }
        }
    }

    __syncthreads();
    float* red = (float*)dyn;           // [128][9] overlay (slot 0 region)
    #pragma unroll
    for (int mf = 0; mf < 2; mf++) {
        const int r0 = warpM * 32 + mf * 16 + gq;
        red[r0 * 9 + warpN * 4 + t]       = sacc[mf][0];
        red[(r0 + 8) * 9 + warpN * 4 + t] = sacc[mf][1];
    }
    __syncthreads();
    if (tid < 128) {
        float a = 0.f;
        #pragma unroll
        for (int c = 0; c < 8; c++) a += red[tid * 9 + c];
        const int s = blockIdx.x * 2 + (tid >> 6);
        const int b = tid & 63;
        spart[(size_t)blockIdx.y * S_ * B_ + (size_t)s * B_ + b] = a;
    }
}

// ---------------------------------------------------------------------------
// Small kernels (unchanged)
// ---------------------------------------------------------------------------
__global__ void havg_kernel(const float* __restrict__ h, float* __restrict__ havg)
{
    int b = blockIdx.x;
    int e = blockIdx.y * 256 + threadIdx.x;
    float s = 0.f;
    for (int si = 0; si < S_; si++)
        s += h[((size_t)si * B_ + b) * E_ + e];
    havg[(size_t)b * E_ + e] = s * (1.f / (float)S_);
}

__global__ __launch_bounds__(256) void softmax_beta_kernel(
    const float* __restrict__ spart,
    const float* __restrict__ hp0, const float* __restrict__ hp1,
    const float* __restrict__ hp2, const float* __restrict__ bh2,
    const float* __restrict__ Wb, const float* __restrict__ bb,
    const float* __restrict__ ba2,
    float* __restrict__ aw_out, float* __restrict__ beta)
{
    int b = blockIdx.x, tid = threadIdx.x;
    __shared__ float sm[256];

    float p = 0.f;
    for (int d = tid; d < D_; d += 256) {
        size_t i = (size_t)b * D_ + d;
        float hv = hp0[i] + hp1[i] + hp2[i] + bh2[d];
        p = fmaf(hv, Wb[d], p);
    }
    sm[tid] = p; __syncthreads();
    for (int o = 128; o > 0; o >>= 1) { if (tid < o) sm[tid] += sm[tid + o]; __syncthreads(); }
    if (tid == 0) beta[b] = 1.f / (1.f + expf(-(sm[0] + bb[0])));
    __syncthreads();

    float v = -3.4e38f;
    if (tid < S_) {
        size_t idx = (size_t)tid * B_ + b;
        v = spart[idx] + spart[(size_t)S_ * B_ + idx] + spart[2 * (size_t)S_ * B_ + idx] + ba2[0];
    }
    sm[tid] = v; __syncthreads();
    for (int o = 128; o > 0; o >>= 1) { if (tid < o) sm[tid] = fmaxf(sm[tid], sm[tid + o]); __syncthreads(); }
    float mx = sm[0]; __syncthreads();
    float e = (tid < S_) ? expf(v - mx) : 0.f;
    sm[tid] = e; __syncthreads();
    for (int o = 128; o > 0; o >>= 1) { if (tid < o) sm[tid] += sm[tid + o]; __syncthreads(); }
    float inv = 1.f / sm[0];
    if (tid < S_) aw_out[(size_t)tid * B_ + b] = e * inv;
}

__global__ void ctx_kernel(const float* __restrict__ h, const float* __restrict__ aw,
                           const float* __restrict__ beta, float* __restrict__ ctx)
{
    int b = blockIdx.x;
    int e = blockIdx.y * 256 + threadIdx.x;
    float s = 0.f;
    for (int si = 0; si < S_; si++)
        s = fmaf(aw[(size_t)si * B_ + b], h[((size_t)si * B_ + b) * E_ + e], s);
    ctx[(size_t)b * E_ + e] = s * beta[b];
}

__global__ __launch_bounds__(256) void argmax_kernel(const float* __restrict__ y, int* __restrict__ amax)
{
    int b = blockIdx.x, tid = threadIdx.x;
    float bm = -3.4e38f; int bi = 0;
    for (int i = tid; i < V_; i += 256) {
        float v = y[(size_t)b * V_ + i];
        if (v > bm) { bm = v; bi = i; }
    }
    __shared__ float sv[256];
    __shared__ int si_[256];
    sv[tid] = bm; si_[tid] = bi; __syncthreads();
    for (int o = 128; o > 0; o >>= 1) {
        if (tid < o) {
            if (sv[tid + o] > sv[tid] || (sv[tid + o] == sv[tid] && si_[tid + o] < si_[tid])) {
                sv[tid] = sv[tid + o]; si_[tid] = si_[tid + o];
            }
        }
        __syncthreads();
    }
    if (tid == 0) amax[b] = si_[0];
}

__global__ void xbuild_kernel(const float* __restrict__ emb, const int* __restrict__ Etm1,
                              const float* __restrict__ ctx, float* __restrict__ x)
{
    int b = blockIdx.x;
    int i = blockIdx.y * 256 + threadIdx.x;
    if (i < W_) x[(size_t)b * WE_ + i] = emb[(size_t)Etm1[b] * W_ + i];
    else        x[(size_t)b * WE_ + i] = ctx[(size_t)b * E_ + (i - W_)];
}

__global__ void lstm_kernel(const float* __restrict__ gp0, const float* __restrict__ gp1,
                            const float* __restrict__ b_ih, const float* __restrict__ b_hh,
                            const float* __restrict__ cp0, const float* __restrict__ cp1,
                            const float* __restrict__ cp2, const float* __restrict__ bc2,
                            float* __restrict__ out, float* __restrict__ z)
{
    const size_t P4 = (size_t)B_ * 4 * D_;
    int b = blockIdx.x;
    int d = blockIdx.y * 256 + threadIdx.x;
    if (d >= D_) return;
    const size_t base = (size_t)b * 4 * D_;
    float gi = gp0[base + d]        + gp0[P4 + base + d]        + gp1[base + d]        + gp1[P4 + base + d]        + b_ih[d]        + b_hh[d];
    float gf = gp0[base + D_ + d]   + gp0[P4 + base + D_ + d]   + gp1[base + D_ + d]   + gp1[P4 + base + D_ + d]   + b_ih[D_ + d]   + b_hh[D_ + d];
    float gg = gp0[base + 2*D_ + d] + gp0[P4 + base + 2*D_ + d] + gp1[base + 2*D_ + d] + gp1[P4 + base + 2*D_ + d] + b_ih[2*D_ + d] + b_hh[2*D_ + d];
    float go = gp0[base + 3*D_ + d] + gp0[P4 + base + 3*D_ + d] + gp1[base + 3*D_ + d] + gp1[P4 + base + 3*D_ + d] + b_ih[3*D_ + d] + b_hh[3*D_ + d];
    size_t ci = (size_t)b * D_ + d;
    float c0 = cp0[ci] + cp1[ci] + cp2[ci] + bc2[d];
    float ig = 1.f / (1.f + expf(-gi));
    float fg = 1.f / (1.f + expf(-gf));
    float gt = tanhf(gg);
    float og = 1.f / (1.f + expf(-go));
    float c = fmaf(fg, c0, ig * gt);
    float ht = og * tanhf(c);
    out[(size_t)B_ * V_ + (size_t)b * D_ + d] = ht;
    out[(size_t)B_ * V_ + (size_t)B_ * D_ + (size_t)b * D_ + d] = c;
    z[(size_t)b * DWE_ + d] = ht;
}

__global__ void zbuild_kernel(const float* __restrict__ emb, const int* __restrict__ amax,
                              const float* __restrict__ ctx, float* __restrict__ z)
{
    int b = blockIdx.x;
    int i = blockIdx.y * 256 + threadIdx.x;
    if (i < W_) z[(size_t)b * DWE_ + D_ + i] = emb[(size_t)amax[b] * W_ + i];
    else        z[(size_t)b * DWE_ + D_ + i] = ctx[(size_t)b * E_ + (i - W_)];
}

// ---------------------------------------------------------------------------
// Launch
// ---------------------------------------------------------------------------
extern "C" void kernel_launch(void* const* d_in, const int* in_sizes, int n_in,
                              void* d_out, int out_size)
{
    const int*   E_tm1 = (const int*)d_in[0];
    const float* y_tm1 = (const float*)d_in[1];
    const float* h     = (const float*)d_in[2];
    const float* emb   = (const float*)d_in[3];
    const float* W_ih  = (const float*)d_in[4];
    const float* b_ih  = (const float*)d_in[5];
    const float* W_hh  = (const float*)d_in[6];
    const float* b_hh  = (const float*)d_in[7];
    const float* W_out = (const float*)d_in[8];
    const float* b_out = (const float*)d_in[9];
    const float* Wh1 = (const float*)d_in[10]; const float* bh1 = (const float*)d_in[11];
    const float* Wh2 = (const float*)d_in[12]; const float* bh2 = (const float*)d_in[13];
    const float* Wc1 = (const float*)d_in[14]; const float* bc1 = (const float*)d_in[15];
    const float* Wc2 = (const float*)d_in[16]; const float* bc2 = (const float*)d_in[17];
    const float* Wa1 = (const float*)d_in[18]; const float* ba1 = (const float*)d_in[19];
    const float* Wa2 = (const float*)d_in[20]; const float* ba2 = (const float*)d_in[21];
    const float* Wb  = (const float*)d_in[22]; const float* bb  = (const float*)d_in[23];
    float* out = (float*)d_out;

    Scratch* s = nullptr;
    cudaGetSymbolAddress((void**)&s, g_s);

    cudaFuncSetAttribute(mma_scores_kernel,
                         cudaFuncAttributeMaxDynamicSharedMemorySize, SC_DYN);

    const int GN_D  = (D_ + 63) / 64;            // 29
    const int GN_4D = (4 * D_ + 127) / 128;      // 57
    const int GN_V  = V_ / 128;                  // 250
    const int CONV_BLK = (S_ * B_ * E_ / 8 + D_ * E_ / 8 + 255) / 256;

    // 0. fp16 preconversion of h and Wa1 key-slice
    conv16_kernel<<<CONV_BLK, 256>>>(h, Wa1, s->h16, s->w16);

    // 1. encoder mean
    havg_kernel<<<dim3(B_, E_ / 256), 256>>>(h, s->havg);

    // 2. init-state layer1 -> partials (KS=3)
    {
        SKJob2 jj;
        jj.j[0] = {s->havg, nullptr, nullptr, nullptr, 0, Wh1, E_, E_, D_, s->skpA[0][0]};
        jj.j[1] = {s->havg, nullptr, nullptr, nullptr, 0, Wc1, E_, E_, D_, s->skpA[1][0]};
        sk_gemm_kernel<64><<<dim3(GN_D, 2, 3), 256>>>(jj);
    }
    // 3. layer2, A = relu(sum of 3 L1 partials + b1) fused (KS=3)
    {
        SKJob2 jj;
        jj.j[0] = {s->skpA[0][0], s->skpA[0][1], s->skpA[0][2], bh1, 1, Wh2, D_, D_, D_, s->skpB[0][0]};
        jj.j[1] = {s->skpA[1][0], s->skpA[1][1], s->skpA[1][2], bc1, 1, Wc2, D_, D_, D_, s->skpB[1][0]};
        sk_gemm_kernel<64><<<dim3(GN_D, 2, 3), 256>>>(jj);
    }
    // 4. qpart partials = (h0 = sum L2 partials + bh2) @ Wa1[:, :D]^T  (KS=3)
    {
        SKJob2 jj;
        jj.j[0] = {s->skpB[0][0], s->skpB[0][1], s->skpB[0][2], bh2, 0, Wa1, D_, DE_, D_, s->skpA[0][0]};
        jj.j[1] = jj.j[0];
        sk_gemm_kernel<64><<<dim3(GN_D, 1, 3), 256>>>(jj);
    }
    // 5. qpart reduce (+ ba1)
    sk_reduce3_kernel<<<(B_ * D_ + 255) / 256, 256>>>(s->skpA[0][0], ba1, s->qpart);

    // 6. fused scores GEMM (cp.async pipeline, 2 blocks/SM)
    mma_scores_kernel<<<dim3(S_ / 2, 3), 256, SC_DYN>>>(
        s->h16, s->w16, s->qpart, Wa2, s->spart);

    // 7. argmax of y_tm1
    argmax_kernel<<<B_, 256>>>(y_tm1, s->amax);

    // 8. softmax + beta (h0 virtual from partials)
    float* aw_out = out + (size_t)B_ * V_ + 2 * (size_t)B_ * D_;
    softmax_beta_kernel<<<B_, 256>>>(s->spart, s->skpB[0][0], s->skpB[0][1], s->skpB[0][2],
                                     bh2, Wb, bb, ba2, aw_out, s->beta);

    // 9. context
    ctx_kernel<<<dim3(B_, E_ / 256), 256>>>(h, aw_out, s->beta, s->ctx);

    // 10. LSTM input + gates (split-K 2 on both jobs)
    xbuild_kernel<<<dim3(B_, WE_ / 256), 256>>>(emb, E_tm1, s->ctx, s->x);
    {
        SKJob2 jj;
        jj.j[0] = {s->x, nullptr, nullptr, nullptr, 0, W_ih, WE_, WE_, 4 * D_, s->gp0[0]};
        jj.j[1] = {s->skpB[0][0], s->skpB[0][1], s->skpB[0][2], bh2, 0, W_hh, D_, D_, 4 * D_, s->gp1[0]};
        sk_gemm_kernel<128><<<dim3(GN_4D, 2, 2), 256>>>(jj);
    }

    // 11. LSTM pointwise (4 gate partials; c0 from partials)
    lstm_kernel<<<dim3(B_, (D_ + 255) / 256), 256>>>(
        s->gp0[0], s->gp1[0], b_ih, b_hh,
        s->skpB[1][0], s->skpB[1][1], s->skpB[1][2], bc2, out, s->z);

    // 12. z tail
    zbuild_kernel<<<dim3(B_, WE_ / 256), 256>>>(emb, s->amax, s->ctx, s->z);

    // 13. logits (split-K 2) + reduce
    {
        SKJob2 jj;
        jj.j[0] = {s->z, nullptr, nullptr, nullptr, 0, W_out, DWE_, DWE_, V_, s->lgp[0]};
        jj.j[1] = jj.j[0];
        sk_gemm_kernel<128><<<dim3(GN_V, 1, 2), 256>>>(jj);
    }
    logits_reduce_kernel<<<(B_ * V_ + 255) / 256, 256>>>(s->lgp[0], b_out, out);
}